// round 1
// baseline (speedup 1.0000x reference)
#include <cuda_runtime.h>
#include <cuda_bf16.h>

// Problem constants (fixed by reference): B=4, T=4096, C=256, H=64
#define BB 4
#define TT 4096
#define CC 256
#define HH 64
#define SCALE 0.0625f   // C**-0.5 = 1/16

// Scratch for K, Q, V projections: [B, T, H] fp32 each = 4MB each.
__device__ float g_k[BB * TT * HH];
__device__ float g_q[BB * TT * HH];
__device__ float g_v[BB * TT * HH];

// ---------------------------------------------------------------------------
// Kernel 1: QKV projection. Each block handles 16 rows of x (staged in smem);
// threads 0..191 each own one (matrix, h) column and accumulate 16 rows.
// ---------------------------------------------------------------------------
__global__ void __launch_bounds__(256) qkv_kernel(
    const float* __restrict__ x,
    const float* __restrict__ Wk, const float* __restrict__ bk,
    const float* __restrict__ Wq, const float* __restrict__ bq,
    const float* __restrict__ Wv, const float* __restrict__ bv)
{
    __shared__ float xs[16][CC];
    const int tid = threadIdx.x;
    const int row0 = blockIdx.x * 16;

    // load 16 rows of x (16*256 floats = 1024 float4)
    const float4* xin = (const float4*)(x + (size_t)row0 * CC);
    float4* xs4 = (float4*)&xs[0][0];
    #pragma unroll
    for (int i = 0; i < 4; i++) {
        xs4[tid + i * 256] = xin[tid + i * 256];
    }
    __syncthreads();

    if (tid < 192) {
        const int m = tid >> 6;      // 0=k, 1=q, 2=v
        const int h = tid & 63;
        const float* __restrict__ W = (m == 0) ? Wk : ((m == 1) ? Wq : Wv);
        const float* __restrict__ bi = (m == 0) ? bk : ((m == 1) ? bq : bv);
        float acc[16];
        const float bias = bi[h];
        #pragma unroll
        for (int r = 0; r < 16; r++) acc[r] = bias;

        #pragma unroll 4
        for (int c = 0; c < CC; c++) {
            const float w = __ldg(&W[c * HH + h]);
            #pragma unroll
            for (int r = 0; r < 16; r++) acc[r] = fmaf(xs[r][c], w, acc[r]);
        }

        float* dst = (m == 0) ? g_k : ((m == 1) ? g_q : g_v);
        #pragma unroll
        for (int r = 0; r < 16; r++) dst[(size_t)(row0 + r) * HH + h] = acc[r];
    }
}

// ---------------------------------------------------------------------------
// Kernel 2: flash-attention with online softmax.
//   scores[t,s] = (k[t] . q[s]) * SCALE ; softmax over s ; out = P @ V.
// Block: 128 threads, 64 t-rows. Thread = (row-pair rp, quad q4).
// Thread owns rows r0=2*rp, r1=r0+1 and columns c = q4 + 4*j (j=0..15).
// ---------------------------------------------------------------------------
#define PAD 68   // smem row stride in floats (68*4 bytes, float4-aligned)

__global__ void __launch_bounds__(128) attn_kernel(float* __restrict__ out)
{
    extern __shared__ float sm[];
    float* Ksh = sm;                 // [64][PAD]
    float* Qsh = sm + 64 * PAD;      // [64][PAD]
    float* Vsh = sm + 2 * 64 * PAD;  // [64][PAD]
    float* Psh = sm + 3 * 64 * PAD;  // [64][PAD]

    const int tid = threadIdx.x;
    const int b   = blockIdx.y;
    const int t0  = blockIdx.x * 64;
    const int q4  = tid & 3;
    const int rp  = tid >> 2;        // 0..31
    const int r0  = rp * 2;
    const int r1  = r0 + 1;

    // Load K tile for this block's 64 rows: 1024 float4
    const float4* kbase = (const float4*)(g_k + (size_t)(b * TT + t0) * HH);
    #pragma unroll
    for (int it = 0; it < 8; it++) {
        int i = tid + it * 128;
        int row = i >> 4, c4 = i & 15;
        *(float4*)&Ksh[row * PAD + c4 * 4] = kbase[row * 16 + c4];
    }

    float m0 = -1e30f, m1 = -1e30f, l0 = 0.f, l1 = 0.f;
    float acc0[16], acc1[16];
    #pragma unroll
    for (int j = 0; j < 16; j++) { acc0[j] = 0.f; acc1[j] = 0.f; }

    const float4* qb = (const float4*)(g_q + (size_t)b * TT * HH);
    const float4* vb = (const float4*)(g_v + (size_t)b * TT * HH);

    for (int s0 = 0; s0 < TT; s0 += 64) {
        __syncthreads();   // protect prev iteration's Qsh/Vsh reads
        {
            const float4* qt = qb + (size_t)s0 * (HH / 4);
            const float4* vt = vb + (size_t)s0 * (HH / 4);
            #pragma unroll
            for (int it = 0; it < 8; it++) {
                int i = tid + it * 128;
                int row = i >> 4, c4 = i & 15;
                *(float4*)&Qsh[row * PAD + c4 * 4] = qt[row * 16 + c4];
                *(float4*)&Vsh[row * PAD + c4 * 4] = vt[row * 16 + c4];
            }
        }
        __syncthreads();

        // ---- stage 1: logits S[r][c] for this tile ----
        float sv0[16], sv1[16];
        #pragma unroll
        for (int j = 0; j < 16; j++) { sv0[j] = 0.f; sv1[j] = 0.f; }

        #pragma unroll 4
        for (int h4 = 0; h4 < 16; h4++) {
            const float4 k0 = *(const float4*)&Ksh[r0 * PAD + h4 * 4];
            const float4 k1 = *(const float4*)&Ksh[r1 * PAD + h4 * 4];
            #pragma unroll
            for (int j = 0; j < 16; j++) {
                const int c = q4 + 4 * j;
                const float4 qv = *(const float4*)&Qsh[c * PAD + h4 * 4];
                sv0[j] = fmaf(k0.x, qv.x, sv0[j]);
                sv0[j] = fmaf(k0.y, qv.y, sv0[j]);
                sv0[j] = fmaf(k0.z, qv.z, sv0[j]);
                sv0[j] = fmaf(k0.w, qv.w, sv0[j]);
                sv1[j] = fmaf(k1.x, qv.x, sv1[j]);
                sv1[j] = fmaf(k1.y, qv.y, sv1[j]);
                sv1[j] = fmaf(k1.z, qv.z, sv1[j]);
                sv1[j] = fmaf(k1.w, qv.w, sv1[j]);
            }
        }

        // ---- online softmax bookkeeping (4 lanes per row) ----
        float tm0 = -1e30f, tm1 = -1e30f;
        #pragma unroll
        for (int j = 0; j < 16; j++) {
            sv0[j] *= SCALE; sv1[j] *= SCALE;
            tm0 = fmaxf(tm0, sv0[j]);
            tm1 = fmaxf(tm1, sv1[j]);
        }
        tm0 = fmaxf(tm0, __shfl_xor_sync(0xffffffffu, tm0, 1));
        tm0 = fmaxf(tm0, __shfl_xor_sync(0xffffffffu, tm0, 2));
        tm1 = fmaxf(tm1, __shfl_xor_sync(0xffffffffu, tm1, 1));
        tm1 = fmaxf(tm1, __shfl_xor_sync(0xffffffffu, tm1, 2));

        const float nm0 = fmaxf(m0, tm0);
        const float nm1 = fmaxf(m1, tm1);

        float sum0 = 0.f, sum1 = 0.f;
        #pragma unroll
        for (int j = 0; j < 16; j++) {
            const float p0 = __expf(sv0[j] - nm0);
            const float p1 = __expf(sv1[j] - nm1);
            sv0[j] = p0; sv1[j] = p1;
            sum0 += p0; sum1 += p1;
        }
        sum0 += __shfl_xor_sync(0xffffffffu, sum0, 1);
        sum0 += __shfl_xor_sync(0xffffffffu, sum0, 2);
        sum1 += __shfl_xor_sync(0xffffffffu, sum1, 1);
        sum1 += __shfl_xor_sync(0xffffffffu, sum1, 2);

        const float f0 = __expf(m0 - nm0);
        const float f1 = __expf(m1 - nm1);
        #pragma unroll
        for (int j = 0; j < 16; j++) { acc0[j] *= f0; acc1[j] *= f1; }
        l0 = l0 * f0 + sum0;
        l1 = l1 * f1 + sum1;
        m0 = nm0; m1 = nm1;

        // stage-1 result to Psh (warp-local rows)
        #pragma unroll
        for (int j = 0; j < 16; j++) {
            Psh[r0 * PAD + q4 + 4 * j] = sv0[j];
            Psh[r1 * PAD + q4 + 4 * j] = sv1[j];
        }
        __syncwarp();

        // ---- stage 2: O += P @ V ; thread owns h = q4 + 4*j ----
        #pragma unroll 4
        for (int c = 0; c < 64; c++) {
            const float p0 = Psh[r0 * PAD + c];
            const float p1 = Psh[r1 * PAD + c];
            #pragma unroll
            for (int j = 0; j < 16; j++) {
                const float v = Vsh[c * PAD + q4 + 4 * j];
                acc0[j] = fmaf(p0, v, acc0[j]);
                acc1[j] = fmaf(p1, v, acc1[j]);
            }
        }
        __syncwarp();   // stage2 reads done before next tile's Psh writes
    }

    // ---- epilogue: normalize + write out ----
    const float inv0 = 1.0f / l0;
    const float inv1 = 1.0f / l1;
    float* ob = out + (size_t)(b * TT + t0) * HH;
    #pragma unroll
    for (int j = 0; j < 16; j++) {
        ob[r0 * HH + q4 + 4 * j] = acc0[j] * inv0;
        ob[r1 * HH + q4 + 4 * j] = acc1[j] * inv1;
    }
}

// ---------------------------------------------------------------------------
extern "C" void kernel_launch(void* const* d_in, const int* in_sizes, int n_in,
                              void* d_out, int out_size)
{
    const float* x  = (const float*)d_in[0];
    const float* Wk = (const float*)d_in[1];
    const float* bk = (const float*)d_in[2];
    const float* Wq = (const float*)d_in[3];
    const float* bq = (const float*)d_in[4];
    const float* Wv = (const float*)d_in[5];
    const float* bv = (const float*)d_in[6];
    float* out = (float*)d_out;

    const int smem_bytes = 4 * 64 * PAD * sizeof(float);  // 69632
    cudaFuncSetAttribute(attn_kernel, cudaFuncAttributeMaxDynamicSharedMemorySize,
                         smem_bytes);

    qkv_kernel<<<(BB * TT) / 16, 256>>>(x, Wk, bk, Wq, bq, Wv, bv);

    dim3 grid(TT / 64, BB);
    attn_kernel<<<grid, 128, smem_bytes>>>(out);
}

// round 3
// speedup vs baseline: 3.0040x; 3.0040x over previous
#include <cuda_runtime.h>
#include <cstdint>

// Problem constants: B=4, T=4096, C=256, H=64
#define BB 4
#define TT 4096
#define CC 256
#define HH 64
#define SCALE 0.0625f   // C**-0.5

// Scratch K,Q,V projections [B,T,H] fp32 (tf32-RNA-rounded values).
__device__ float g_k[BB * TT * HH];
__device__ float g_q[BB * TT * HH];
__device__ float g_v[BB * TT * HH];

__device__ __forceinline__ uint32_t f2tf32(float f) {
    uint32_t r; asm("cvt.rna.tf32.f32 %0, %1;" : "=r"(r) : "f"(f)); return r;
}

// m16n8k8 tf32 mma: D += A*B, row.col. c[4] fp32, a[4]/b[2] tf32 bits.
__device__ __forceinline__ void mma_tf32(float* c, const uint32_t* a,
                                         uint32_t b0, uint32_t b1) {
    asm volatile(
        "mma.sync.aligned.m16n8k8.row.col.f32.tf32.tf32.f32 "
        "{%0,%1,%2,%3}, {%4,%5,%6,%7}, {%8,%9}, {%0,%1,%2,%3};"
        : "+f"(c[0]), "+f"(c[1]), "+f"(c[2]), "+f"(c[3])
        : "r"(a[0]), "r"(a[1]), "r"(a[2]), "r"(a[3]), "r"(b0), "r"(b1));
}

// ---------------------------------------------------------------------------
// Kernel 1: QKV projection (SIMT; outputs tf32-RNA values)
// ---------------------------------------------------------------------------
__global__ void __launch_bounds__(256) qkv_kernel(
    const float* __restrict__ x,
    const float* __restrict__ Wk, const float* __restrict__ bk,
    const float* __restrict__ Wq, const float* __restrict__ bq,
    const float* __restrict__ Wv, const float* __restrict__ bv)
{
    __shared__ float xs[16][CC];
    const int tid = threadIdx.x;
    const int row0 = blockIdx.x * 16;

    const float4* xin = (const float4*)(x + (size_t)row0 * CC);
    float4* xs4 = (float4*)&xs[0][0];
    #pragma unroll
    for (int i = 0; i < 4; i++) xs4[tid + i * 256] = xin[tid + i * 256];
    __syncthreads();

    if (tid < 192) {
        const int m = tid >> 6;
        const int h = tid & 63;
        const float* __restrict__ W  = (m == 0) ? Wk : ((m == 1) ? Wq : Wv);
        const float* __restrict__ bi = (m == 0) ? bk : ((m == 1) ? bq : bv);
        float acc[16];
        const float bias = bi[h];
        #pragma unroll
        for (int r = 0; r < 16; r++) acc[r] = bias;

        #pragma unroll 4
        for (int c = 0; c < CC; c++) {
            const float w = __ldg(&W[c * HH + h]);
            #pragma unroll
            for (int r = 0; r < 16; r++) acc[r] = fmaf(xs[r][c], w, acc[r]);
        }
        float* dst = (m == 0) ? g_k : ((m == 1) ? g_q : g_v);
        #pragma unroll
        for (int r = 0; r < 16; r++)
            dst[(size_t)(row0 + r) * HH + h] = __uint_as_float(f2tf32(acc[r]));
    }
}

// ---------------------------------------------------------------------------
// Kernel 2: tensor-core flash attention via mma.sync tf32 (no-max softmax).
// Block 256 thr = 8 warps. CTA handles 128 t-rows; loop 32 s-tiles of 128.
//   MMA1: warp (wr=warp&3, wc=warp>>2) computes S[32t x 64s], K-dim 64.
//   softmax: exp in regs, row-partials accumulated in regs, P -> SMEM (tf32).
//   MMA2: warp computes O[32t x 32h] (wr rows, wc h-half), K-dim 128, accum
//         in fp32 C fragments across all 32 tiles (no rescale needed).
// SMEM strides: K/Q/V = 72 floats/row, P = 136 floats/row (conflict-free for
// the m16n8k8 fragment access patterns).
// ---------------------------------------------------------------------------
#define KQV_STR 72
#define P_STR   136
#define K_OFF   0
#define Q_OFF   (128 * KQV_STR)            // 9216
#define V_OFF   (Q_OFF + 128 * KQV_STR)    // 18432
#define P_OFF   (V_OFF + 128 * KQV_STR)    // 27648
#define L_OFF   (P_OFF + 128 * P_STR)      // 45056
#define SMEM_FLOATS (L_OFF + 256)
#define SMEM_BYTES  (SMEM_FLOATS * 4)      // 181248

__global__ void __launch_bounds__(256, 1) attn_kernel(float* __restrict__ out)
{
    extern __shared__ float sm[];
    float* Ks = sm + K_OFF;
    float* Qs = sm + Q_OFF;
    float* Vs = sm + V_OFF;
    float* Ps = sm + P_OFF;
    float* Ls = sm + L_OFF;

    const int tid  = threadIdx.x;
    const int warp = tid >> 5;
    const int lane = tid & 31;
    const int wr = warp & 3;      // t-row block (32 rows)
    const int wc = warp >> 2;     // s half (MMA1) / h half (MMA2)
    const int g  = lane >> 2;     // groupID
    const int t4 = lane & 3;      // threadID-in-group
    const int b  = blockIdx.y;
    const int t0 = blockIdx.x * 128;

    // ---- load K tile [128][64] once ----
    {
        const float4* kb = (const float4*)(g_k + (size_t)(b * TT + t0) * HH);
        #pragma unroll
        for (int it = 0; it < 8; it++) {
            int i = tid + it * 256;
            int row = i >> 4, c4 = i & 15;
            *(float4*)&Ks[row * KQV_STR + c4 * 4] = kb[i];
        }
    }

    float o[2][4][4];
    #pragma unroll
    for (int mi = 0; mi < 2; mi++)
        #pragma unroll
        for (int nj = 0; nj < 4; nj++)
            #pragma unroll
            for (int e = 0; e < 4; e++) o[mi][nj][e] = 0.0f;

    float lsum[2][2] = {{0.f, 0.f}, {0.f, 0.f}};

    const float* qb = g_q + (size_t)b * TT * HH;
    const float* vb = g_v + (size_t)b * TT * HH;

    for (int tile = 0; tile < 32; tile++) {
        const int s0 = tile * 128;
        __syncthreads();   // prev MMA2 done reading Ps/Qs/Vs

        // ---- load Q,V tiles [128][64] ----
        {
            const float4* qt = (const float4*)(qb + (size_t)s0 * HH);
            const float4* vt = (const float4*)(vb + (size_t)s0 * HH);
            #pragma unroll
            for (int it = 0; it < 8; it++) {
                int i = tid + it * 256;
                int row = i >> 4, c4 = i & 15;
                *(float4*)&Qs[row * KQV_STR + c4 * 4] = qt[i];
                *(float4*)&Vs[row * KQV_STR + c4 * 4] = vt[i];
            }
        }
        __syncthreads();

        // ---- MMA1: S[32t x 64s] = K . Q^T, K-dim 64 ----
        float c[2][8][4];
        #pragma unroll
        for (int mi = 0; mi < 2; mi++)
            #pragma unroll
            for (int ni = 0; ni < 8; ni++)
                #pragma unroll
                for (int e = 0; e < 4; e++) c[mi][ni][e] = 0.0f;

        const int arow = wr * 32 + g;
        const int scol = wc * 64 + g;
        #pragma unroll
        for (int k8 = 0; k8 < 8; k8++) {
            const int k0 = k8 * 8;
            uint32_t a[2][4];
            #pragma unroll
            for (int mi = 0; mi < 2; mi++) {
                const float* base = &Ks[(arow + mi * 16) * KQV_STR + k0 + t4];
                a[mi][0] = __float_as_uint(base[0]);
                a[mi][1] = __float_as_uint(base[8 * KQV_STR]);
                a[mi][2] = __float_as_uint(base[4]);
                a[mi][3] = __float_as_uint(base[8 * KQV_STR + 4]);
            }
            #pragma unroll
            for (int ni = 0; ni < 8; ni++) {
                const float* qbase = &Qs[(scol + ni * 8) * KQV_STR + k0 + t4];
                const uint32_t b0 = __float_as_uint(qbase[0]);
                const uint32_t b1 = __float_as_uint(qbase[4]);
                mma_tf32(c[0][ni], a[0], b0, b1);
                mma_tf32(c[1][ni], a[1], b0, b1);
            }
        }

        // ---- softmax (no max subtraction) + restage P to SMEM ----
        #pragma unroll
        for (int mi = 0; mi < 2; mi++) {
            const int prow = wr * 32 + mi * 16 + g;
            float r0 = 0.f, r1 = 0.f;
            #pragma unroll
            for (int ni = 0; ni < 8; ni++) {
                const float e0 = __expf(c[mi][ni][0] * SCALE);
                const float e1 = __expf(c[mi][ni][1] * SCALE);
                const float e2 = __expf(c[mi][ni][2] * SCALE);
                const float e3 = __expf(c[mi][ni][3] * SCALE);
                r0 += e0 + e1;
                r1 += e2 + e3;
                const int pcol = wc * 64 + ni * 8 + 2 * t4;
                float2 lo, hi;
                lo.x = __uint_as_float(f2tf32(e0));
                lo.y = __uint_as_float(f2tf32(e1));
                hi.x = __uint_as_float(f2tf32(e2));
                hi.y = __uint_as_float(f2tf32(e3));
                *(float2*)&Ps[prow * P_STR + pcol]       = lo;
                *(float2*)&Ps[(prow + 8) * P_STR + pcol] = hi;
            }
            lsum[mi][0] += r0;
            lsum[mi][1] += r1;
        }
        __syncthreads();

        // ---- MMA2: O[32t x 32h] += P . V, K-dim 128 ----
        const int prow0 = wr * 32 + g;
        const int hcol  = wc * 32 + g;
        #pragma unroll
        for (int k16 = 0; k16 < 16; k16++) {
            const int k0 = k16 * 8;
            uint32_t a[2][4];
            #pragma unroll
            for (int mi = 0; mi < 2; mi++) {
                const float* base = &Ps[(prow0 + mi * 16) * P_STR + k0 + t4];
                a[mi][0] = __float_as_uint(base[0]);
                a[mi][1] = __float_as_uint(base[8 * P_STR]);
                a[mi][2] = __float_as_uint(base[4]);
                a[mi][3] = __float_as_uint(base[8 * P_STR + 4]);
            }
            #pragma unroll
            for (int nj = 0; nj < 4; nj++) {
                const float* vb2 = &Vs[(k0 + t4) * KQV_STR + hcol + nj * 8 - g + g];
                const uint32_t b0 = __float_as_uint(vb2[0]);
                const uint32_t b1 = __float_as_uint(vb2[4 * KQV_STR]);
                mma_tf32(o[0][nj], a[0], b0, b1);
                mma_tf32(o[1][nj], a[1], b0, b1);
            }
        }
    }

    // ---- row-sum reduction: quad shfl, then combine the two s-half warps ----
    #pragma unroll
    for (int mi = 0; mi < 2; mi++)
        #pragma unroll
        for (int v = 0; v < 2; v++) {
            float s = lsum[mi][v];
            s += __shfl_xor_sync(0xffffffffu, s, 1);
            s += __shfl_xor_sync(0xffffffffu, s, 2);
            lsum[mi][v] = s;
        }
    if (t4 == 0) {
        #pragma unroll
        for (int mi = 0; mi < 2; mi++) {
            Ls[(wr * 32 + mi * 16 + g) * 2 + wc]     = lsum[mi][0];
            Ls[(wr * 32 + mi * 16 + g + 8) * 2 + wc] = lsum[mi][1];
        }
    }
    __syncthreads();

    // ---- epilogue: normalize + store ----
    #pragma unroll
    for (int mi = 0; mi < 2; mi++) {
        #pragma unroll
        for (int v = 0; v < 2; v++) {
            const int row = wr * 32 + mi * 16 + g + v * 8;
            const float inv = 1.0f / (Ls[row * 2] + Ls[row * 2 + 1]);
            float* ob = out + ((size_t)(b * TT) + t0 + row) * HH;
            #pragma unroll
            for (int nj = 0; nj < 4; nj++) {
                float2 w;
                w.x = o[mi][nj][2 * v + 0] * inv;
                w.y = o[mi][nj][2 * v + 1] * inv;
                *(float2*)&ob[wc * 32 + nj * 8 + 2 * t4] = w;
            }
        }
    }
}

// ---------------------------------------------------------------------------
extern "C" void kernel_launch(void* const* d_in, const int* in_sizes, int n_in,
                              void* d_out, int out_size)
{
    const float* x  = (const float*)d_in[0];
    const float* Wk = (const float*)d_in[1];
    const float* bk = (const float*)d_in[2];
    const float* Wq = (const float*)d_in[3];
    const float* bq = (const float*)d_in[4];
    const float* Wv = (const float*)d_in[5];
    const float* bv = (const float*)d_in[6];
    float* out = (float*)d_out;

    cudaFuncSetAttribute(attn_kernel, cudaFuncAttributeMaxDynamicSharedMemorySize,
                         SMEM_BYTES);

    qkv_kernel<<<(BB * TT) / 16, 256>>>(x, Wk, bk, Wq, bq, Wv, bv);

    dim3 grid(TT / 128, BB);
    attn_kernel<<<grid, 256, SMEM_BYTES>>>(out);
}

// round 4
// speedup vs baseline: 3.3280x; 1.1079x over previous
#include <cuda_runtime.h>
#include <cstdint>

// Problem constants: B=4, T=4096, C=256, H=64
#define BB 4
#define TT 4096
#define CC 256
#define HH 64
// k is pre-scaled by log2(e)/16 so softmax is a bare ex2 of the mma result.
#define KSCALE 0.09016844005556021f

// Scratch: tf32-rounded projections + split-s partial outputs.
__device__ float g_k[BB * TT * HH];
__device__ float g_q[BB * TT * HH];
__device__ float g_v[BB * TT * HH];
__device__ float g_opart[2 * BB * TT * HH];   // 8MB
__device__ float g_lpart[2 * BB * TT];

__device__ __forceinline__ uint32_t f2tf32(float f) {
    uint32_t r; asm("cvt.rna.tf32.f32 %0, %1;" : "=r"(r) : "f"(f)); return r;
}
__device__ __forceinline__ float ex2f(float x) {
    float r; asm("ex2.approx.f32 %0, %1;" : "=f"(r) : "f"(x)); return r;
}
// m16n8k8 tf32 mma: D += A*B (row.col)
__device__ __forceinline__ void mma_tf32(float* c, const uint32_t* a,
                                         uint32_t b0, uint32_t b1) {
    asm volatile(
        "mma.sync.aligned.m16n8k8.row.col.f32.tf32.tf32.f32 "
        "{%0,%1,%2,%3}, {%4,%5,%6,%7}, {%8,%9}, {%0,%1,%2,%3};"
        : "+f"(c[0]), "+f"(c[1]), "+f"(c[2]), "+f"(c[3])
        : "r"(a[0]), "r"(a[1]), "r"(a[2]), "r"(a[3]), "r"(b0), "r"(b1));
}

// ---------------------------------------------------------------------------
// Kernel 1: QKV projection (fp32 SIMT, tf32-RNA outputs; k pre-scaled)
// ---------------------------------------------------------------------------
__global__ void __launch_bounds__(256) qkv_kernel(
    const float* __restrict__ x,
    const float* __restrict__ Wk, const float* __restrict__ bk,
    const float* __restrict__ Wq, const float* __restrict__ bq,
    const float* __restrict__ Wv, const float* __restrict__ bv)
{
    __shared__ float xs[16][CC];
    const int tid = threadIdx.x;
    const int row0 = blockIdx.x * 16;

    const float4* xin = (const float4*)(x + (size_t)row0 * CC);
    float4* xs4 = (float4*)&xs[0][0];
    #pragma unroll
    for (int i = 0; i < 4; i++) xs4[tid + i * 256] = xin[tid + i * 256];
    __syncthreads();

    if (tid < 192) {
        const int m = tid >> 6;
        const int h = tid & 63;
        const float* __restrict__ W  = (m == 0) ? Wk : ((m == 1) ? Wq : Wv);
        const float* __restrict__ bi = (m == 0) ? bk : ((m == 1) ? bq : bv);
        float acc[16];
        const float bias = bi[h];
        #pragma unroll
        for (int r = 0; r < 16; r++) acc[r] = bias;

        #pragma unroll 4
        for (int c = 0; c < CC; c++) {
            const float w = __ldg(&W[c * HH + h]);
            #pragma unroll
            for (int r = 0; r < 16; r++) acc[r] = fmaf(xs[r][c], w, acc[r]);
        }
        float* dst = (m == 0) ? g_k : ((m == 1) ? g_q : g_v);
        const float sc = (m == 0) ? KSCALE : 1.0f;
        #pragma unroll
        for (int r = 0; r < 16; r++)
            dst[(size_t)(row0 + r) * HH + h] = __uint_as_float(f2tf32(acc[r] * sc));
    }
}

// ---------------------------------------------------------------------------
// Kernel 2: tf32 mma flash attention, 2-CTA/SM layout, split-s partials.
// CTA: 256 thr (8 warps), 128 t-rows, 32 s-tiles of 64 (z picks half range).
// warp = (wr 0..3 : 32-row block, wc 0..1 : s-half in MMA1 / h-half in MMA2).
// MMA1: S[32t x 32s] (K-dim 64) -> exp -> P smem. MMA2: O[32t x 32h], K=64.
// smem: Ks[128][68] Qs[64][68] Vs[64][72] Ps[128][68] Ls[256]  = 104 KB.
// ---------------------------------------------------------------------------
#define KSTR 68
#define QSTR 68
#define VSTR 72
#define PSTR 68
#define K_SOFF 0
#define Q_SOFF (128 * KSTR)
#define V_SOFF (Q_SOFF + 64 * QSTR)
#define P_SOFF (V_SOFF + 64 * VSTR)
#define L_SOFF (P_SOFF + 128 * PSTR)
#define SMEM_FLOATS (L_SOFF + 256)
#define SMEM_BYTES  (SMEM_FLOATS * 4)   // 106496

__global__ void __launch_bounds__(256, 2) attn_kernel()
{
    extern __shared__ float sm[];
    float* Ks = sm + K_SOFF;
    float* Qs = sm + Q_SOFF;
    float* Vs = sm + V_SOFF;
    float* Ps = sm + P_SOFF;
    float* Ls = sm + L_SOFF;

    const int tid  = threadIdx.x;
    const int warp = tid >> 5;
    const int lane = tid & 31;
    const int wr = warp & 3;
    const int wc = warp >> 2;
    const int g  = lane >> 2;
    const int t4 = lane & 3;
    const int b  = blockIdx.y;
    const int t0 = blockIdx.x * 128;
    const int z  = blockIdx.z;

    // ---- stage K tile [128][64] ----
    {
        const float4* kb = (const float4*)(g_k + (size_t)(b * TT + t0) * HH);
        #pragma unroll
        for (int it = 0; it < 8; it++) {
            int i = tid + it * 256;
            int row = i >> 4, c4 = i & 15;
            *(float4*)&Ks[row * KSTR + c4 * 4] = kb[i];
        }
    }

    float o[2][4][4];
    #pragma unroll
    for (int mi = 0; mi < 2; mi++)
        #pragma unroll
        for (int nj = 0; nj < 4; nj++)
            #pragma unroll
            for (int e = 0; e < 4; e++) o[mi][nj][e] = 0.0f;
    float lsum[2][2] = {{0.f, 0.f}, {0.f, 0.f}};

    const float* qb = g_q + (size_t)b * TT * HH;
    const float* vb = g_v + (size_t)b * TT * HH;
    const int arow = wr * 32 + g;

    for (int tile = 0; tile < 32; tile++) {
        const int s0 = (z * 32 + tile) * 64;
        __syncthreads();   // prev MMA2 reads of Vs/Ps done

        // ---- stage Q,V tiles [64][64] ----
        {
            const float4* qt = (const float4*)(qb + (size_t)s0 * HH);
            const float4* vt = (const float4*)(vb + (size_t)s0 * HH);
            #pragma unroll
            for (int it = 0; it < 4; it++) {
                int i = tid + it * 256;
                int row = i >> 4, c4 = i & 15;
                *(float4*)&Qs[row * QSTR + c4 * 4] = qt[i];
                *(float4*)&Vs[row * VSTR + c4 * 4] = vt[i];
            }
        }
        __syncthreads();

        // ---- MMA1: S[32t x 32s], K-dim 64 ----
        float c[2][4][4];
        #pragma unroll
        for (int mi = 0; mi < 2; mi++)
            #pragma unroll
            for (int ni = 0; ni < 4; ni++)
                #pragma unroll
                for (int e = 0; e < 4; e++) c[mi][ni][e] = 0.0f;

        const int scol = wc * 32 + g;
        #pragma unroll
        for (int k8 = 0; k8 < 8; k8++) {
            const int k0 = k8 * 8;
            uint32_t a[2][4];
            #pragma unroll
            for (int mi = 0; mi < 2; mi++) {
                const float* base = &Ks[(arow + mi * 16) * KSTR + k0 + t4];
                a[mi][0] = __float_as_uint(base[0]);
                a[mi][1] = __float_as_uint(base[8 * KSTR]);
                a[mi][2] = __float_as_uint(base[4]);
                a[mi][3] = __float_as_uint(base[8 * KSTR + 4]);
            }
            #pragma unroll
            for (int ni = 0; ni < 4; ni++) {
                const float* qp = &Qs[(scol + ni * 8) * QSTR + k0 + t4];
                const uint32_t b0 = __float_as_uint(qp[0]);
                const uint32_t b1 = __float_as_uint(qp[4]);
                mma_tf32(c[0][ni], a[0], b0, b1);
                mma_tf32(c[1][ni], a[1], b0, b1);
            }
        }

        // ---- exp (k pre-scaled by log2e/16 -> bare ex2) + P store ----
        #pragma unroll
        for (int mi = 0; mi < 2; mi++) {
            const int prow = wr * 32 + mi * 16 + g;
            #pragma unroll
            for (int ni = 0; ni < 4; ni++) {
                const float e0 = ex2f(c[mi][ni][0]);
                const float e1 = ex2f(c[mi][ni][1]);
                const float e2 = ex2f(c[mi][ni][2]);
                const float e3 = ex2f(c[mi][ni][3]);
                lsum[mi][0] += e0 + e1;
                lsum[mi][1] += e2 + e3;
                const int pcol = wc * 32 + ni * 8 + 2 * t4;
                float2 lo, hi;
                lo.x = __uint_as_float(f2tf32(e0));
                lo.y = __uint_as_float(f2tf32(e1));
                hi.x = __uint_as_float(f2tf32(e2));
                hi.y = __uint_as_float(f2tf32(e3));
                *(float2*)&Ps[prow * PSTR + pcol]       = lo;
                *(float2*)&Ps[(prow + 8) * PSTR + pcol] = hi;
            }
        }
        __syncthreads();

        // ---- MMA2: O[32t x 32h] += P[32t x 64s] . V[64s x 32h] ----
        #pragma unroll
        for (int k8 = 0; k8 < 8; k8++) {
            const int k0 = k8 * 8;
            uint32_t pa[2][4];
            #pragma unroll
            for (int mi = 0; mi < 2; mi++) {
                const float* base = &Ps[(arow + mi * 16) * PSTR + k0 + t4];
                pa[mi][0] = __float_as_uint(base[0]);
                pa[mi][1] = __float_as_uint(base[8 * PSTR]);
                pa[mi][2] = __float_as_uint(base[4]);
                pa[mi][3] = __float_as_uint(base[8 * PSTR + 4]);
            }
            #pragma unroll
            for (int nj = 0; nj < 4; nj++) {
                const float* vp = &Vs[(k0 + t4) * VSTR + wc * 32 + nj * 8 + g];
                const uint32_t b0 = __float_as_uint(vp[0]);
                const uint32_t b1 = __float_as_uint(vp[4 * VSTR]);
                mma_tf32(o[0][nj], pa[0], b0, b1);
                mma_tf32(o[1][nj], pa[1], b0, b1);
            }
        }
    }

    // ---- epilogue: partial row sums + partial O to scratch ----
    #pragma unroll
    for (int mi = 0; mi < 2; mi++)
        #pragma unroll
        for (int v = 0; v < 2; v++) {
            float s = lsum[mi][v];
            s += __shfl_xor_sync(0xffffffffu, s, 1);
            s += __shfl_xor_sync(0xffffffffu, s, 2);
            lsum[mi][v] = s;
        }

    __syncthreads();   // all MMA2 reads of Ps done; reuse Ps as O staging
    #pragma unroll
    for (int mi = 0; mi < 2; mi++) {
        const int row = wr * 32 + mi * 16 + g;
        #pragma unroll
        for (int nj = 0; nj < 4; nj++) {
            const int col = wc * 32 + nj * 8 + 2 * t4;
            Ps[row * PSTR + col]           = o[mi][nj][0];
            Ps[row * PSTR + col + 1]       = o[mi][nj][1];
            Ps[(row + 8) * PSTR + col]     = o[mi][nj][2];
            Ps[(row + 8) * PSTR + col + 1] = o[mi][nj][3];
        }
        if (t4 == 0) {
            Ls[(row)     * 2 + wc] = lsum[mi][0];
            Ls[(row + 8) * 2 + wc] = lsum[mi][1];
        }
    }
    __syncthreads();

    float4* os = (float4*)(g_opart + (size_t)z * (BB * TT * HH)
                           + (size_t)(b * TT + t0) * HH);
    #pragma unroll
    for (int it = 0; it < 8; it++) {
        int i = tid + it * 256;
        int row = i >> 4, c4 = i & 15;
        os[i] = *(float4*)&Ps[row * PSTR + c4 * 4];
    }
    if (tid < 128)
        g_lpart[z * (BB * TT) + b * TT + t0 + tid] = Ls[tid * 2] + Ls[tid * 2 + 1];
}

// ---------------------------------------------------------------------------
// Kernel 3: combine the two s-splits and normalize.
// ---------------------------------------------------------------------------
__global__ void __launch_bounds__(256) combine_kernel(float* __restrict__ out)
{
    const int i4 = blockIdx.x * 256 + threadIdx.x;    // float4 index
    const int row = i4 >> 4;                          // 16 float4 per 64-col row
    const float inv = 1.0f / (g_lpart[row] + g_lpart[BB * TT + row]);
    const float4 a = ((const float4*)g_opart)[i4];
    const float4 c = ((const float4*)(g_opart + (size_t)BB * TT * HH))[i4];
    float4 r;
    r.x = (a.x + c.x) * inv;
    r.y = (a.y + c.y) * inv;
    r.z = (a.z + c.z) * inv;
    r.w = (a.w + c.w) * inv;
    ((float4*)out)[i4] = r;
}

// ---------------------------------------------------------------------------
extern "C" void kernel_launch(void* const* d_in, const int* in_sizes, int n_in,
                              void* d_out, int out_size)
{
    const float* x  = (const float*)d_in[0];
    const float* Wk = (const float*)d_in[1];
    const float* bk = (const float*)d_in[2];
    const float* Wq = (const float*)d_in[3];
    const float* bq = (const float*)d_in[4];
    const float* Wv = (const float*)d_in[5];
    const float* bv = (const float*)d_in[6];
    float* out = (float*)d_out;

    cudaFuncSetAttribute(attn_kernel, cudaFuncAttributeMaxDynamicSharedMemorySize,
                         SMEM_BYTES);

    qkv_kernel<<<(BB * TT) / 16, 256>>>(x, Wk, bk, Wq, bq, Wv, bv);

    dim3 grid(TT / 128, BB, 2);
    attn_kernel<<<grid, 256, SMEM_BYTES>>>();

    combine_kernel<<<(BB * TT * HH) / (4 * 256), 256>>>(out);
}

// round 5
// speedup vs baseline: 4.5777x; 1.3755x over previous
#include <cuda_runtime.h>
#include <cstdint>

// Problem constants: B=4, T=4096, C=256, H=64
#define BB 4
#define TT 4096
#define CC 256
#define HH 64
// k is pre-scaled by log2(e)/16 so softmax is a bare ex2 of the mma result.
#define KSCALE 0.09016844005556021f

// Scratch: tf32-rounded projections + split-s partial outputs.
__device__ float g_k[BB * TT * HH];
__device__ float g_q[BB * TT * HH];
__device__ float g_v[BB * TT * HH];
__device__ float g_opart[2 * BB * TT * HH];   // 8MB
__device__ float g_lpart[2 * BB * TT];
__device__ float g_wt[192 * CC];              // W^T combined [h'][c], tf32
__device__ float g_bias[192];

__device__ __forceinline__ uint32_t f2tf32(float f) {
    uint32_t r; asm("cvt.rna.tf32.f32 %0, %1;" : "=r"(r) : "f"(f)); return r;
}
__device__ __forceinline__ float ex2f(float x) {
    float r; asm("ex2.approx.f32 %0, %1;" : "=f"(r) : "f"(x)); return r;
}
// m16n8k8 tf32 mma: D += A*B (row.col)
__device__ __forceinline__ void mma_tf32(float* c, const uint32_t* a,
                                         uint32_t b0, uint32_t b1) {
    asm volatile(
        "mma.sync.aligned.m16n8k8.row.col.f32.tf32.tf32.f32 "
        "{%0,%1,%2,%3}, {%4,%5,%6,%7}, {%8,%9}, {%0,%1,%2,%3};"
        : "+f"(c[0]), "+f"(c[1]), "+f"(c[2]), "+f"(c[3])
        : "r"(a[0]), "r"(a[1]), "r"(a[2]), "r"(a[3]), "r"(b0), "r"(b1));
}

// ---------------------------------------------------------------------------
// Kernel 0: build W^T [192][256] (tf32-RNA) + combined bias.
// row j = m*64+h (m: 0=k 1=q 2=v). block j, 256 threads over c.
// ---------------------------------------------------------------------------
__global__ void __launch_bounds__(256) wprep_kernel(
    const float* __restrict__ Wk, const float* __restrict__ bk,
    const float* __restrict__ Wq, const float* __restrict__ bq,
    const float* __restrict__ Wv, const float* __restrict__ bv)
{
    const int j = blockIdx.x;
    const int m = j >> 6;
    const int h = j & 63;
    const int c = threadIdx.x;
    const float* W = (m == 0) ? Wk : ((m == 1) ? Wq : Wv);
    g_wt[j * CC + c] = __uint_as_float(f2tf32(W[c * HH + h]));
    if (c == 0) {
        const float* bi = (m == 0) ? bk : ((m == 1) ? bq : bv);
        g_bias[j] = bi[h];
    }
}

// ---------------------------------------------------------------------------
// Kernel 1: QKV projection as tf32 GEMM [16384,256]x[256,192].
// 128 CTAs x 512 thr (16 warps, 4x4). CTA tile 128 rows x 192 cols.
// K-loop: 4 chunks of 64; xs[128][68], ws[192][68] staged in smem.
// ---------------------------------------------------------------------------
#define XSTR 68
#define WSTR 68
#define QKV_SMEM_FLOATS (128 * XSTR + 192 * WSTR)
#define QKV_SMEM_BYTES  (QKV_SMEM_FLOATS * 4)   // 87040

__global__ void __launch_bounds__(512, 1) qkv_mma_kernel(const float* __restrict__ x)
{
    extern __shared__ float sm[];
    float* xs = sm;
    float* ws = sm + 128 * XSTR;

    const int tid  = threadIdx.x;
    const int warp = tid >> 5;
    const int lane = tid & 31;
    const int wr = warp & 3;      // 32-row block
    const int wc = warp >> 2;     // 48-col block
    const int g  = lane >> 2;
    const int t4 = lane & 3;
    const int row0 = blockIdx.x * 128;

    float c[2][6][4];
    #pragma unroll
    for (int mi = 0; mi < 2; mi++)
        #pragma unroll
        for (int ni = 0; ni < 6; ni++)
            #pragma unroll
            for (int e = 0; e < 4; e++) c[mi][ni][e] = 0.0f;

    const float4* x4  = (const float4*)x;
    const float4* wt4 = (const float4*)g_wt;
    const int arow = wr * 32 + g;

    #pragma unroll
    for (int kc = 0; kc < 4; kc++) {
        __syncthreads();
        // stage x chunk [128][64], tf32-rounded
        #pragma unroll
        for (int it = 0; it < 4; it++) {
            int i = tid + it * 512;          // 0..2047
            int row = i >> 4, c4 = i & 15;
            float4 v = x4[(size_t)(row0 + row) * (CC / 4) + kc * 16 + c4];
            v.x = __uint_as_float(f2tf32(v.x));
            v.y = __uint_as_float(f2tf32(v.y));
            v.z = __uint_as_float(f2tf32(v.z));
            v.w = __uint_as_float(f2tf32(v.w));
            *(float4*)&xs[row * XSTR + c4 * 4] = v;
        }
        // stage W^T chunk [192][64] (already tf32)
        #pragma unroll
        for (int it = 0; it < 6; it++) {
            int i = tid + it * 512;          // 0..3071
            int j = i >> 4, c4 = i & 15;
            *(float4*)&ws[j * WSTR + c4 * 4] = wt4[j * (CC / 4) + kc * 16 + c4];
        }
        __syncthreads();

        #pragma unroll
        for (int k8 = 0; k8 < 8; k8++) {
            const int k0 = k8 * 8;
            uint32_t a[2][4];
            #pragma unroll
            for (int mi = 0; mi < 2; mi++) {
                const float* base = &xs[(arow + mi * 16) * XSTR + k0 + t4];
                a[mi][0] = __float_as_uint(base[0]);
                a[mi][1] = __float_as_uint(base[8 * XSTR]);
                a[mi][2] = __float_as_uint(base[4]);
                a[mi][3] = __float_as_uint(base[8 * XSTR + 4]);
            }
            #pragma unroll
            for (int ni = 0; ni < 6; ni++) {
                const float* wp = &ws[(wc * 48 + ni * 8 + g) * WSTR + k0 + t4];
                const uint32_t b0 = __float_as_uint(wp[0]);
                const uint32_t b1 = __float_as_uint(wp[4]);
                mma_tf32(c[0][ni], a[0], b0, b1);
                mma_tf32(c[1][ni], a[1], b0, b1);
            }
        }
    }

    // epilogue: +bias, k-scale, tf32 round, scatter to g_k/g_q/g_v
    #pragma unroll
    for (int ni = 0; ni < 6; ni++) {
        const int col0 = wc * 48 + ni * 8;           // multiple of 8: no straddle
        const int m = col0 >> 6;
        float* dst = (m == 0) ? g_k : ((m == 1) ? g_q : g_v);
        const float sc = (m == 0) ? KSCALE : 1.0f;
        const int h = (col0 & 63) + 2 * t4;
        const float b0 = g_bias[col0 + 2 * t4];
        const float b1 = g_bias[col0 + 2 * t4 + 1];
        #pragma unroll
        for (int mi = 0; mi < 2; mi++) {
            const int row = row0 + wr * 32 + mi * 16 + g;
            float2 lo, hi;
            lo.x = __uint_as_float(f2tf32((c[mi][ni][0] + b0) * sc));
            lo.y = __uint_as_float(f2tf32((c[mi][ni][1] + b1) * sc));
            hi.x = __uint_as_float(f2tf32((c[mi][ni][2] + b0) * sc));
            hi.y = __uint_as_float(f2tf32((c[mi][ni][3] + b1) * sc));
            *(float2*)&dst[(size_t)row * HH + h]       = lo;
            *(float2*)&dst[(size_t)(row + 8) * HH + h] = hi;
        }
    }
}

// ---------------------------------------------------------------------------
// Kernel 2: tf32 mma flash attention, 2 CTA/SM, split-s partials (unchanged).
// ---------------------------------------------------------------------------
#define KSTR 68
#define QSTR 68
#define VSTR 72
#define PSTR 68
#define K_SOFF 0
#define Q_SOFF (128 * KSTR)
#define V_SOFF (Q_SOFF + 64 * QSTR)
#define P_SOFF (V_SOFF + 64 * VSTR)
#define L_SOFF (P_SOFF + 128 * PSTR)
#define SMEM_FLOATS (L_SOFF + 256)
#define SMEM_BYTES  (SMEM_FLOATS * 4)   // 106496

__global__ void __launch_bounds__(256, 2) attn_kernel()
{
    extern __shared__ float sm[];
    float* Ks = sm + K_SOFF;
    float* Qs = sm + Q_SOFF;
    float* Vs = sm + V_SOFF;
    float* Ps = sm + P_SOFF;
    float* Ls = sm + L_SOFF;

    const int tid  = threadIdx.x;
    const int warp = tid >> 5;
    const int lane = tid & 31;
    const int wr = warp & 3;
    const int wc = warp >> 2;
    const int g  = lane >> 2;
    const int t4 = lane & 3;
    const int b  = blockIdx.y;
    const int t0 = blockIdx.x * 128;
    const int z  = blockIdx.z;

    {
        const float4* kb = (const float4*)(g_k + (size_t)(b * TT + t0) * HH);
        #pragma unroll
        for (int it = 0; it < 8; it++) {
            int i = tid + it * 256;
            int row = i >> 4, c4 = i & 15;
            *(float4*)&Ks[row * KSTR + c4 * 4] = kb[i];
        }
    }

    float o[2][4][4];
    #pragma unroll
    for (int mi = 0; mi < 2; mi++)
        #pragma unroll
        for (int nj = 0; nj < 4; nj++)
            #pragma unroll
            for (int e = 0; e < 4; e++) o[mi][nj][e] = 0.0f;
    float lsum[2][2] = {{0.f, 0.f}, {0.f, 0.f}};

    const float* qb = g_q + (size_t)b * TT * HH;
    const float* vb = g_v + (size_t)b * TT * HH;
    const int arow = wr * 32 + g;

    for (int tile = 0; tile < 32; tile++) {
        const int s0 = (z * 32 + tile) * 64;
        __syncthreads();

        {
            const float4* qt = (const float4*)(qb + (size_t)s0 * HH);
            const float4* vt = (const float4*)(vb + (size_t)s0 * HH);
            #pragma unroll
            for (int it = 0; it < 4; it++) {
                int i = tid + it * 256;
                int row = i >> 4, c4 = i & 15;
                *(float4*)&Qs[row * QSTR + c4 * 4] = qt[i];
                *(float4*)&Vs[row * VSTR + c4 * 4] = vt[i];
            }
        }
        __syncthreads();

        float c[2][4][4];
        #pragma unroll
        for (int mi = 0; mi < 2; mi++)
            #pragma unroll
            for (int ni = 0; ni < 4; ni++)
                #pragma unroll
                for (int e = 0; e < 4; e++) c[mi][ni][e] = 0.0f;

        const int scol = wc * 32 + g;
        #pragma unroll
        for (int k8 = 0; k8 < 8; k8++) {
            const int k0 = k8 * 8;
            uint32_t a[2][4];
            #pragma unroll
            for (int mi = 0; mi < 2; mi++) {
                const float* base = &Ks[(arow + mi * 16) * KSTR + k0 + t4];
                a[mi][0] = __float_as_uint(base[0]);
                a[mi][1] = __float_as_uint(base[8 * KSTR]);
                a[mi][2] = __float_as_uint(base[4]);
                a[mi][3] = __float_as_uint(base[8 * KSTR + 4]);
            }
            #pragma unroll
            for (int ni = 0; ni < 4; ni++) {
                const float* qp = &Qs[(scol + ni * 8) * QSTR + k0 + t4];
                const uint32_t b0 = __float_as_uint(qp[0]);
                const uint32_t b1 = __float_as_uint(qp[4]);
                mma_tf32(c[0][ni], a[0], b0, b1);
                mma_tf32(c[1][ni], a[1], b0, b1);
            }
        }

        #pragma unroll
        for (int mi = 0; mi < 2; mi++) {
            const int prow = wr * 32 + mi * 16 + g;
            #pragma unroll
            for (int ni = 0; ni < 4; ni++) {
                const float e0 = ex2f(c[mi][ni][0]);
                const float e1 = ex2f(c[mi][ni][1]);
                const float e2 = ex2f(c[mi][ni][2]);
                const float e3 = ex2f(c[mi][ni][3]);
                lsum[mi][0] += e0 + e1;
                lsum[mi][1] += e2 + e3;
                const int pcol = wc * 32 + ni * 8 + 2 * t4;
                float2 lo, hi;
                lo.x = __uint_as_float(f2tf32(e0));
                lo.y = __uint_as_float(f2tf32(e1));
                hi.x = __uint_as_float(f2tf32(e2));
                hi.y = __uint_as_float(f2tf32(e3));
                *(float2*)&Ps[prow * PSTR + pcol]       = lo;
                *(float2*)&Ps[(prow + 8) * PSTR + pcol] = hi;
            }
        }
        __syncthreads();

        #pragma unroll
        for (int k8 = 0; k8 < 8; k8++) {
            const int k0 = k8 * 8;
            uint32_t pa[2][4];
            #pragma unroll
            for (int mi = 0; mi < 2; mi++) {
                const float* base = &Ps[(arow + mi * 16) * PSTR + k0 + t4];
                pa[mi][0] = __float_as_uint(base[0]);
                pa[mi][1] = __float_as_uint(base[8 * PSTR]);
                pa[mi][2] = __float_as_uint(base[4]);
                pa[mi][3] = __float_as_uint(base[8 * PSTR + 4]);
            }
            #pragma unroll
            for (int nj = 0; nj < 4; nj++) {
                const float* vp = &Vs[(k0 + t4) * VSTR + wc * 32 + nj * 8 + g];
                const uint32_t b0 = __float_as_uint(vp[0]);
                const uint32_t b1 = __float_as_uint(vp[4 * VSTR]);
                mma_tf32(o[0][nj], pa[0], b0, b1);
                mma_tf32(o[1][nj], pa[1], b0, b1);
            }
        }
    }

    #pragma unroll
    for (int mi = 0; mi < 2; mi++)
        #pragma unroll
        for (int v = 0; v < 2; v++) {
            float s = lsum[mi][v];
            s += __shfl_xor_sync(0xffffffffu, s, 1);
            s += __shfl_xor_sync(0xffffffffu, s, 2);
            lsum[mi][v] = s;
        }

    __syncthreads();
    #pragma unroll
    for (int mi = 0; mi < 2; mi++) {
        const int row = wr * 32 + mi * 16 + g;
        #pragma unroll
        for (int nj = 0; nj < 4; nj++) {
            const int col = wc * 32 + nj * 8 + 2 * t4;
            Ps[row * PSTR + col]           = o[mi][nj][0];
            Ps[row * PSTR + col + 1]       = o[mi][nj][1];
            Ps[(row + 8) * PSTR + col]     = o[mi][nj][2];
            Ps[(row + 8) * PSTR + col + 1] = o[mi][nj][3];
        }
        if (t4 == 0) {
            Ls[(row)     * 2 + wc] = lsum[mi][0];
            Ls[(row + 8) * 2 + wc] = lsum[mi][1];
        }
    }
    __syncthreads();

    float4* os = (float4*)(g_opart + (size_t)z * (BB * TT * HH)
                           + (size_t)(b * TT + t0) * HH);
    #pragma unroll
    for (int it = 0; it < 8; it++) {
        int i = tid + it * 256;
        int row = i >> 4, c4 = i & 15;
        os[i] = *(float4*)&Ps[row * PSTR + c4 * 4];
    }
    if (tid < 128)
        g_lpart[z * (BB * TT) + b * TT + t0 + tid] = Ls[tid * 2] + Ls[tid * 2 + 1];
}

// ---------------------------------------------------------------------------
// Kernel 3: combine the two s-splits and normalize.
// ---------------------------------------------------------------------------
__global__ void __launch_bounds__(256) combine_kernel(float* __restrict__ out)
{
    const int i4 = blockIdx.x * 256 + threadIdx.x;
    const int row = i4 >> 4;
    const float inv = 1.0f / (g_lpart[row] + g_lpart[BB * TT + row]);
    const float4 a = ((const float4*)g_opart)[i4];
    const float4 c = ((const float4*)(g_opart + (size_t)BB * TT * HH))[i4];
    float4 r;
    r.x = (a.x + c.x) * inv;
    r.y = (a.y + c.y) * inv;
    r.z = (a.z + c.z) * inv;
    r.w = (a.w + c.w) * inv;
    ((float4*)out)[i4] = r;
}

// ---------------------------------------------------------------------------
extern "C" void kernel_launch(void* const* d_in, const int* in_sizes, int n_in,
                              void* d_out, int out_size)
{
    const float* x  = (const float*)d_in[0];
    const float* Wk = (const float*)d_in[1];
    const float* bk = (const float*)d_in[2];
    const float* Wq = (const float*)d_in[3];
    const float* bq = (const float*)d_in[4];
    const float* Wv = (const float*)d_in[5];
    const float* bv = (const float*)d_in[6];
    float* out = (float*)d_out;

    cudaFuncSetAttribute(qkv_mma_kernel, cudaFuncAttributeMaxDynamicSharedMemorySize,
                         QKV_SMEM_BYTES);
    cudaFuncSetAttribute(attn_kernel, cudaFuncAttributeMaxDynamicSharedMemorySize,
                         SMEM_BYTES);

    wprep_kernel<<<192, 256>>>(Wk, bk, Wq, bq, Wv, bv);
    qkv_mma_kernel<<<(BB * TT) / 128, 512, QKV_SMEM_BYTES>>>(x);

    dim3 grid(TT / 128, BB, 2);
    attn_kernel<<<grid, 256, SMEM_BYTES>>>();

    combine_kernel<<<(BB * TT * HH) / (4 * 256), 256>>>(out);
}

// round 6
// speedup vs baseline: 4.9243x; 1.0757x over previous
#include <cuda_runtime.h>
#include <cstdint>

// Problem constants: B=4, T=4096, C=256, H=64
#define BB 4
#define TT 4096
#define CC 256
#define HH 64
// k is pre-scaled by log2(e)/16 so softmax is a bare ex2 of the mma result.
#define KSCALE 0.09016844005556021f

// Scratch: tf32-rounded projections + split-s partial outputs.
__device__ float g_k[BB * TT * HH];
__device__ float g_q[BB * TT * HH];
__device__ float g_v[BB * TT * HH];
__device__ float g_opart[2 * BB * TT * HH];   // 8MB
__device__ float g_lpart[2 * BB * TT];
__device__ float g_wt[192 * CC];              // W^T combined [h'][c], tf32
__device__ float g_bias[192];

__device__ __forceinline__ uint32_t f2tf32(float f) {
    uint32_t r; asm("cvt.rna.tf32.f32 %0, %1;" : "=r"(r) : "f"(f)); return r;
}
__device__ __forceinline__ float ex2f(float x) {
    float r; asm("ex2.approx.f32 %0, %1;" : "=f"(r) : "f"(x)); return r;
}
__device__ __forceinline__ uint32_t smem_u32(const void* p) {
    uint32_t a;
    asm("{ .reg .u64 t; cvta.to.shared.u64 t, %1; cvt.u32.u64 %0, t; }" : "=r"(a) : "l"(p));
    return a;
}
__device__ __forceinline__ void cp_async16(uint32_t dst, const void* src) {
    asm volatile("cp.async.cg.shared.global [%0], [%1], 16;"
                 :: "r"(dst), "l"(src) : "memory");
}
#define CP_COMMIT() asm volatile("cp.async.commit_group;" ::: "memory")
#define CP_WAIT1()  asm volatile("cp.async.wait_group 1;" ::: "memory")
// m16n8k8 tf32 mma: D += A*B (row.col)
__device__ __forceinline__ void mma_tf32(float* c, const uint32_t* a,
                                         uint32_t b0, uint32_t b1) {
    asm volatile(
        "mma.sync.aligned.m16n8k8.row.col.f32.tf32.tf32.f32 "
        "{%0,%1,%2,%3}, {%4,%5,%6,%7}, {%8,%9}, {%0,%1,%2,%3};"
        : "+f"(c[0]), "+f"(c[1]), "+f"(c[2]), "+f"(c[3])
        : "r"(a[0]), "r"(a[1]), "r"(a[2]), "r"(a[3]), "r"(b0), "r"(b1));
}

// ---------------------------------------------------------------------------
// Kernel 0: build W^T [192][256] (tf32-RNA) + combined bias.
// ---------------------------------------------------------------------------
__global__ void __launch_bounds__(256) wprep_kernel(
    const float* __restrict__ Wk, const float* __restrict__ bk,
    const float* __restrict__ Wq, const float* __restrict__ bq,
    const float* __restrict__ Wv, const float* __restrict__ bv)
{
    const int j = blockIdx.x;
    const int m = j >> 6;
    const int h = j & 63;
    const int c = threadIdx.x;
    const float* W = (m == 0) ? Wk : ((m == 1) ? Wq : Wv);
    g_wt[j * CC + c] = __uint_as_float(f2tf32(W[c * HH + h]));
    if (c == 0) {
        const float* bi = (m == 0) ? bk : ((m == 1) ? bq : bv);
        g_bias[j] = bi[h];
    }
}

// ---------------------------------------------------------------------------
// Kernel 1: QKV projection as tf32 GEMM [16384,256]x[256,192]. (unchanged)
// ---------------------------------------------------------------------------
#define XSTR 68
#define WSTR 68
#define QKV_SMEM_BYTES ((128 * XSTR + 192 * WSTR) * 4)   // 87040

__global__ void __launch_bounds__(512, 1) qkv_mma_kernel(const float* __restrict__ x)
{
    extern __shared__ float sm[];
    float* xs = sm;
    float* ws = sm + 128 * XSTR;

    const int tid  = threadIdx.x;
    const int warp = tid >> 5;
    const int lane = tid & 31;
    const int wr = warp & 3;
    const int wc = warp >> 2;
    const int g  = lane >> 2;
    const int t4 = lane & 3;
    const int row0 = blockIdx.x * 128;

    float c[2][6][4];
    #pragma unroll
    for (int mi = 0; mi < 2; mi++)
        #pragma unroll
        for (int ni = 0; ni < 6; ni++)
            #pragma unroll
            for (int e = 0; e < 4; e++) c[mi][ni][e] = 0.0f;

    const float4* x4  = (const float4*)x;
    const float4* wt4 = (const float4*)g_wt;
    const int arow = wr * 32 + g;

    #pragma unroll
    for (int kc = 0; kc < 4; kc++) {
        __syncthreads();
        #pragma unroll
        for (int it = 0; it < 4; it++) {
            int i = tid + it * 512;
            int row = i >> 4, c4 = i & 15;
            float4 v = x4[(size_t)(row0 + row) * (CC / 4) + kc * 16 + c4];
            v.x = __uint_as_float(f2tf32(v.x));
            v.y = __uint_as_float(f2tf32(v.y));
            v.z = __uint_as_float(f2tf32(v.z));
            v.w = __uint_as_float(f2tf32(v.w));
            *(float4*)&xs[row * XSTR + c4 * 4] = v;
        }
        #pragma unroll
        for (int it = 0; it < 6; it++) {
            int i = tid + it * 512;
            int j = i >> 4, c4 = i & 15;
            *(float4*)&ws[j * WSTR + c4 * 4] = wt4[j * (CC / 4) + kc * 16 + c4];
        }
        __syncthreads();

        #pragma unroll
        for (int k8 = 0; k8 < 8; k8++) {
            const int k0 = k8 * 8;
            uint32_t a[2][4];
            #pragma unroll
            for (int mi = 0; mi < 2; mi++) {
                const float* base = &xs[(arow + mi * 16) * XSTR + k0 + t4];
                a[mi][0] = __float_as_uint(base[0]);
                a[mi][1] = __float_as_uint(base[8 * XSTR]);
                a[mi][2] = __float_as_uint(base[4]);
                a[mi][3] = __float_as_uint(base[8 * XSTR + 4]);
            }
            #pragma unroll
            for (int ni = 0; ni < 6; ni++) {
                const float* wp = &ws[(wc * 48 + ni * 8 + g) * WSTR + k0 + t4];
                const uint32_t b0 = __float_as_uint(wp[0]);
                const uint32_t b1 = __float_as_uint(wp[4]);
                mma_tf32(c[0][ni], a[0], b0, b1);
                mma_tf32(c[1][ni], a[1], b0, b1);
            }
        }
    }

    #pragma unroll
    for (int ni = 0; ni < 6; ni++) {
        const int col0 = wc * 48 + ni * 8;
        const int m = col0 >> 6;
        float* dst = (m == 0) ? g_k : ((m == 1) ? g_q : g_v);
        const float sc = (m == 0) ? KSCALE : 1.0f;
        const int h = (col0 & 63) + 2 * t4;
        const float b0 = g_bias[col0 + 2 * t4];
        const float b1 = g_bias[col0 + 2 * t4 + 1];
        #pragma unroll
        for (int mi = 0; mi < 2; mi++) {
            const int row = row0 + wr * 32 + mi * 16 + g;
            float2 lo, hi;
            lo.x = __uint_as_float(f2tf32((c[mi][ni][0] + b0) * sc));
            lo.y = __uint_as_float(f2tf32((c[mi][ni][1] + b1) * sc));
            hi.x = __uint_as_float(f2tf32((c[mi][ni][2] + b0) * sc));
            hi.y = __uint_as_float(f2tf32((c[mi][ni][3] + b1) * sc));
            *(float2*)&dst[(size_t)row * HH + h]       = lo;
            *(float2*)&dst[(size_t)(row + 8) * HH + h] = hi;
        }
    }
}

// ---------------------------------------------------------------------------
// Kernel 2: tf32 mma flash attention, v2.
//  8 warps x 16 t-rows, K-frags in registers, warp-private P, cp.async
//  double-buffered Q/V, one __syncthreads per tile. 2 CTA/SM.
// ---------------------------------------------------------------------------
#define QSTR 68
#define VSTR 72
#define PSTR 72
#define Q_SOFF(buf) ((buf) * 64 * QSTR)
#define V_SOFF(buf) (2 * 64 * QSTR + (buf) * 64 * VSTR)
#define P_SOFF      (2 * 64 * QSTR + 2 * 64 * VSTR)
#define L_SOFF      (P_SOFF + 128 * PSTR)
#define ATTN_SMEM_FLOATS (L_SOFF + 128)
#define ATTN_SMEM_BYTES  (ATTN_SMEM_FLOATS * 4)   // 109056

__global__ void __launch_bounds__(256, 2) attn_kernel()
{
    extern __shared__ float sm[];
    const uint32_t sbase = smem_u32(sm);
    float* Ps = sm + P_SOFF;
    float* Ls = sm + L_SOFF;

    const int tid  = threadIdx.x;
    const int warp = tid >> 5;
    const int lane = tid & 31;
    const int g  = lane >> 2;
    const int t4 = lane & 3;
    const int b  = blockIdx.y;
    const int t0 = blockIdx.x * 128;
    const int z  = blockIdx.z;

    const float* qb = g_q + (size_t)b * TT * HH;
    const float* vb = g_v + (size_t)b * TT * HH;

    // --- cp.async stagers: thread covers 4 chunks of Q and 4 of V per tile ---
    // chunk i in [0,1024): row = i>>4, c4 = i&15.
    auto issue_tile = [&](int tile, int buf) {
        const int s0 = (z * 32 + tile) * 64;
        #pragma unroll
        for (int it = 0; it < 4; it++) {
            int i = tid + it * 256;
            int row = i >> 4, c4 = i & 15;
            cp_async16(sbase + (Q_SOFF(buf) + row * QSTR + c4 * 4) * 4,
                       qb + (size_t)(s0 + row) * HH + c4 * 4);
            cp_async16(sbase + (V_SOFF(buf) + row * VSTR + c4 * 4) * 4,
                       vb + (size_t)(s0 + row) * HH + c4 * 4);
        }
        CP_COMMIT();
    };

    issue_tile(0, 0);
    issue_tile(1, 1);

    // --- K fragments to registers: warp owns rows [warp*16, warp*16+16) ---
    uint32_t kf[8][4];
    {
        const float* kb = g_k + (size_t)(b * TT + t0 + warp * 16) * HH;
        #pragma unroll
        for (int k8 = 0; k8 < 8; k8++) {
            const int k0 = k8 * 8 + t4;
            kf[k8][0] = __float_as_uint(kb[(size_t)g * HH + k0]);
            kf[k8][1] = __float_as_uint(kb[(size_t)(g + 8) * HH + k0]);
            kf[k8][2] = __float_as_uint(kb[(size_t)g * HH + k0 + 4]);
            kf[k8][3] = __float_as_uint(kb[(size_t)(g + 8) * HH + k0 + 4]);
        }
    }

    float o[8][4];
    #pragma unroll
    for (int nj = 0; nj < 8; nj++)
        #pragma unroll
        for (int e = 0; e < 4; e++) o[nj][e] = 0.0f;
    float lsum0 = 0.f, lsum1 = 0.f;

    float* Pw = Ps + warp * 16 * PSTR;     // warp-private P rows

    CP_WAIT1();
    __syncthreads();

    for (int tile = 0; tile < 32; tile++) {
        const int p = tile & 1;
        const float* Qs = sm + Q_SOFF(p);
        const float* Vs = sm + V_SOFF(p);

        // ---- MMA1: S[16t x 64s] = Kfrag . Q^T ----
        float c[8][4];
        #pragma unroll
        for (int ni = 0; ni < 8; ni++)
            #pragma unroll
            for (int e = 0; e < 4; e++) c[ni][e] = 0.0f;

        #pragma unroll
        for (int k8 = 0; k8 < 8; k8++) {
            const int k0 = k8 * 8;
            #pragma unroll
            for (int ni = 0; ni < 8; ni++) {
                const float* qp = &Qs[(ni * 8 + g) * QSTR + k0 + t4];
                mma_tf32(c[ni], kf[k8],
                         __float_as_uint(qp[0]), __float_as_uint(qp[4]));
            }
        }

        // ---- exp + warp-private P write ----
        #pragma unroll
        for (int ni = 0; ni < 8; ni++) {
            const float e0 = ex2f(c[ni][0]);
            const float e1 = ex2f(c[ni][1]);
            const float e2 = ex2f(c[ni][2]);
            const float e3 = ex2f(c[ni][3]);
            lsum0 += e0 + e1;
            lsum1 += e2 + e3;
            const int pcol = ni * 8 + 2 * t4;
            float2 lo, hi;
            lo.x = __uint_as_float(f2tf32(e0));
            lo.y = __uint_as_float(f2tf32(e1));
            hi.x = __uint_as_float(f2tf32(e2));
            hi.y = __uint_as_float(f2tf32(e3));
            *(float2*)&Pw[g * PSTR + pcol]       = lo;
            *(float2*)&Pw[(g + 8) * PSTR + pcol] = hi;
        }
        __syncwarp();

        // ---- MMA2: O[16t x 64h] += P . V ----
        #pragma unroll
        for (int k8 = 0; k8 < 8; k8++) {
            const int k0 = k8 * 8;
            uint32_t pa[4];
            const float* pb = &Pw[g * PSTR + k0 + t4];
            pa[0] = __float_as_uint(pb[0]);
            pa[1] = __float_as_uint(pb[8 * PSTR]);
            pa[2] = __float_as_uint(pb[4]);
            pa[3] = __float_as_uint(pb[8 * PSTR + 4]);
            #pragma unroll
            for (int nj = 0; nj < 8; nj++) {
                const float* vp = &Vs[(k0 + t4) * VSTR + nj * 8 + g];
                mma_tf32(o[nj], pa,
                         __float_as_uint(vp[0]), __float_as_uint(vp[4 * VSTR]));
            }
        }

        __syncthreads();               // all warps done with Qs[p], Vs[p], own P
        const int nt = (tile + 2 < 32) ? (tile + 2) : 31;   // harmless re-issue
        issue_tile(nt, p);
        CP_WAIT1();
        __syncthreads();               // tile+1 buffer visible to all
    }

    // ---- epilogue: partial row sums + partial O (direct stores) ----
    lsum0 += __shfl_xor_sync(0xffffffffu, lsum0, 1);
    lsum0 += __shfl_xor_sync(0xffffffffu, lsum0, 2);
    lsum1 += __shfl_xor_sync(0xffffffffu, lsum1, 1);
    lsum1 += __shfl_xor_sync(0xffffffffu, lsum1, 2);

    const int row = t0 + warp * 16 + g;
    if (t4 == 0) {
        g_lpart[z * (BB * TT) + b * TT + row]     = lsum0;
        g_lpart[z * (BB * TT) + b * TT + row + 8] = lsum1;
    }
    float* ob = g_opart + (size_t)z * (BB * TT * HH) + (size_t)(b * TT + row) * HH;
    #pragma unroll
    for (int nj = 0; nj < 8; nj++) {
        const int col = nj * 8 + 2 * t4;
        *(float2*)&ob[col]           = make_float2(o[nj][0], o[nj][1]);
        *(float2*)&ob[8 * HH + col]  = make_float2(o[nj][2], o[nj][3]);
    }
    (void)Ls;
}

// ---------------------------------------------------------------------------
// Kernel 3: combine the two s-splits and normalize.
// ---------------------------------------------------------------------------
__global__ void __launch_bounds__(256) combine_kernel(float* __restrict__ out)
{
    const int i4 = blockIdx.x * 256 + threadIdx.x;
    const int row = i4 >> 4;
    const float inv = 1.0f / (g_lpart[row] + g_lpart[BB * TT + row]);
    const float4 a = ((const float4*)g_opart)[i4];
    const float4 c = ((const float4*)(g_opart + (size_t)BB * TT * HH))[i4];
    float4 r;
    r.x = (a.x + c.x) * inv;
    r.y = (a.y + c.y) * inv;
    r.z = (a.z + c.z) * inv;
    r.w = (a.w + c.w) * inv;
    ((float4*)out)[i4] = r;
}

// ---------------------------------------------------------------------------
extern "C" void kernel_launch(void* const* d_in, const int* in_sizes, int n_in,
                              void* d_out, int out_size)
{
    const float* x  = (const float*)d_in[0];
    const float* Wk = (const float*)d_in[1];
    const float* bk = (const float*)d_in[2];
    const float* Wq = (const float*)d_in[3];
    const float* bq = (const float*)d_in[4];
    const float* Wv = (const float*)d_in[5];
    const float* bv = (const float*)d_in[6];
    float* out = (float*)d_out;

    cudaFuncSetAttribute(qkv_mma_kernel, cudaFuncAttributeMaxDynamicSharedMemorySize,
                         QKV_SMEM_BYTES);
    cudaFuncSetAttribute(attn_kernel, cudaFuncAttributeMaxDynamicSharedMemorySize,
                         ATTN_SMEM_BYTES);

    wprep_kernel<<<192, 256>>>(Wk, bk, Wq, bq, Wv, bv);
    qkv_mma_kernel<<<(BB * TT) / 128, 512, QKV_SMEM_BYTES>>>(x);

    dim3 grid(TT / 128, BB, 2);
    attn_kernel<<<grid, 256, ATTN_SMEM_BYTES>>>();

    combine_kernel<<<(BB * TT * HH) / (4 * 256), 256>>>(out);
}

// round 7
// speedup vs baseline: 8.3559x; 1.6969x over previous
#include <cuda_runtime.h>
#include <cuda_fp16.h>
#include <cstdint>

// Problem constants: B=4, T=4096, C=256, H=64
#define BB 4
#define TT 4096
#define CC 256
#define HH 64
// k is pre-scaled by log2(e)/16 so softmax is a bare ex2 of the mma result.
#define KSCALE 0.09016844005556021f

// Scratch: fp16 projections (+ transposed V) + split-s partial outputs.
__device__ __half g_k[BB * TT * HH];
__device__ __half g_q[BB * TT * HH];
__device__ __half g_v[BB * TT * HH];
__device__ __half g_vt[BB * HH * TT];         // [b][h][t]
__device__ float  g_opart[2 * BB * TT * HH];  // 8MB
__device__ float  g_lpart[2 * BB * TT];
__device__ float  g_wt[192 * CC];             // W^T combined [h'][c], tf32
__device__ float  g_bias[192];

__device__ __forceinline__ uint32_t f2tf32(float f) {
    uint32_t r; asm("cvt.rna.tf32.f32 %0, %1;" : "=r"(r) : "f"(f)); return r;
}
__device__ __forceinline__ float ex2f(float x) {
    float r; asm("ex2.approx.f32 %0, %1;" : "=f"(r) : "f"(x)); return r;
}
__device__ __forceinline__ uint32_t pack_h2(float lo, float hi) {
    uint32_t r;
    asm("cvt.rn.f16x2.f32 %0, %1, %2;" : "=r"(r) : "f"(hi), "f"(lo));
    return r;
}
__device__ __forceinline__ uint32_t smem_u32(const void* p) {
    uint32_t a;
    asm("{ .reg .u64 t; cvta.to.shared.u64 t, %1; cvt.u32.u64 %0, t; }" : "=r"(a) : "l"(p));
    return a;
}
__device__ __forceinline__ void cp_async16(uint32_t dst, const void* src) {
    asm volatile("cp.async.cg.shared.global [%0], [%1], 16;"
                 :: "r"(dst), "l"(src) : "memory");
}
#define CP_COMMIT() asm volatile("cp.async.commit_group;" ::: "memory")
#define CP_WAIT1()  asm volatile("cp.async.wait_group 1;" ::: "memory")

// tf32 m16n8k8 (used by QKV GEMM)
__device__ __forceinline__ void mma_tf32(float* c, const uint32_t* a,
                                         uint32_t b0, uint32_t b1) {
    asm volatile(
        "mma.sync.aligned.m16n8k8.row.col.f32.tf32.tf32.f32 "
        "{%0,%1,%2,%3}, {%4,%5,%6,%7}, {%8,%9}, {%0,%1,%2,%3};"
        : "+f"(c[0]), "+f"(c[1]), "+f"(c[2]), "+f"(c[3])
        : "r"(a[0]), "r"(a[1]), "r"(a[2]), "r"(a[3]), "r"(b0), "r"(b1));
}
// fp16 m16n8k16 with fp32 accum (attention)
__device__ __forceinline__ void mma_f16(float* c, const uint32_t* a,
                                        uint32_t b0, uint32_t b1) {
    asm volatile(
        "mma.sync.aligned.m16n8k16.row.col.f32.f16.f16.f32 "
        "{%0,%1,%2,%3}, {%4,%5,%6,%7}, {%8,%9}, {%0,%1,%2,%3};"
        : "+f"(c[0]), "+f"(c[1]), "+f"(c[2]), "+f"(c[3])
        : "r"(a[0]), "r"(a[1]), "r"(a[2]), "r"(a[3]), "r"(b0), "r"(b1));
}

// ---------------------------------------------------------------------------
// Kernel 0: build W^T [192][256] (tf32-RNA) + combined bias.
// ---------------------------------------------------------------------------
__global__ void __launch_bounds__(256) wprep_kernel(
    const float* __restrict__ Wk, const float* __restrict__ bk,
    const float* __restrict__ Wq, const float* __restrict__ bq,
    const float* __restrict__ Wv, const float* __restrict__ bv)
{
    const int j = blockIdx.x;
    const int m = j >> 6;
    const int h = j & 63;
    const int c = threadIdx.x;
    const float* W = (m == 0) ? Wk : ((m == 1) ? Wq : Wv);
    g_wt[j * CC + c] = __uint_as_float(f2tf32(W[c * HH + h]));
    if (c == 0) {
        const float* bi = (m == 0) ? bk : ((m == 1) ? bq : bv);
        g_bias[j] = bi[h];
    }
}

// ---------------------------------------------------------------------------
// Kernel 1: QKV projection as tf32 GEMM [16384,256]x[256,192]; fp16 outputs.
// ---------------------------------------------------------------------------
#define XSTR 68
#define WSTR 68
#define QKV_SMEM_BYTES ((128 * XSTR + 192 * WSTR) * 4)   // 87040

__global__ void __launch_bounds__(512, 1) qkv_mma_kernel(const float* __restrict__ x)
{
    extern __shared__ float sm[];
    float* xs = sm;
    float* ws = sm + 128 * XSTR;

    const int tid  = threadIdx.x;
    const int warp = tid >> 5;
    const int lane = tid & 31;
    const int wr = warp & 3;
    const int wc = warp >> 2;
    const int g  = lane >> 2;
    const int t4 = lane & 3;
    const int row0 = blockIdx.x * 128;

    float c[2][6][4];
    #pragma unroll
    for (int mi = 0; mi < 2; mi++)
        #pragma unroll
        for (int ni = 0; ni < 6; ni++)
            #pragma unroll
            for (int e = 0; e < 4; e++) c[mi][ni][e] = 0.0f;

    const float4* x4  = (const float4*)x;
    const float4* wt4 = (const float4*)g_wt;
    const int arow = wr * 32 + g;

    #pragma unroll
    for (int kc = 0; kc < 4; kc++) {
        __syncthreads();
        #pragma unroll
        for (int it = 0; it < 4; it++) {
            int i = tid + it * 512;
            int row = i >> 4, c4 = i & 15;
            float4 v = x4[(size_t)(row0 + row) * (CC / 4) + kc * 16 + c4];
            v.x = __uint_as_float(f2tf32(v.x));
            v.y = __uint_as_float(f2tf32(v.y));
            v.z = __uint_as_float(f2tf32(v.z));
            v.w = __uint_as_float(f2tf32(v.w));
            *(float4*)&xs[row * XSTR + c4 * 4] = v;
        }
        #pragma unroll
        for (int it = 0; it < 6; it++) {
            int i = tid + it * 512;
            int j = i >> 4, c4 = i & 15;
            *(float4*)&ws[j * WSTR + c4 * 4] = wt4[j * (CC / 4) + kc * 16 + c4];
        }
        __syncthreads();

        #pragma unroll
        for (int k8 = 0; k8 < 8; k8++) {
            const int k0 = k8 * 8;
            uint32_t a[2][4];
            #pragma unroll
            for (int mi = 0; mi < 2; mi++) {
                const float* base = &xs[(arow + mi * 16) * XSTR + k0 + t4];
                a[mi][0] = __float_as_uint(base[0]);
                a[mi][1] = __float_as_uint(base[8 * XSTR]);
                a[mi][2] = __float_as_uint(base[4]);
                a[mi][3] = __float_as_uint(base[8 * XSTR + 4]);
            }
            #pragma unroll
            for (int ni = 0; ni < 6; ni++) {
                const float* wp = &ws[(wc * 48 + ni * 8 + g) * WSTR + k0 + t4];
                const uint32_t b0 = __float_as_uint(wp[0]);
                const uint32_t b1 = __float_as_uint(wp[4]);
                mma_tf32(c[0][ni], a[0], b0, b1);
                mma_tf32(c[1][ni], a[1], b0, b1);
            }
        }
    }

    // epilogue: +bias, k-scale, fp16 round, scatter to g_k/g_q/g_v
    #pragma unroll
    for (int ni = 0; ni < 6; ni++) {
        const int col0 = wc * 48 + ni * 8;
        const int m = col0 >> 6;
        __half* dst = (m == 0) ? g_k : ((m == 1) ? g_q : g_v);
        const float sc = (m == 0) ? KSCALE : 1.0f;
        const int h = (col0 & 63) + 2 * t4;
        const float b0 = g_bias[col0 + 2 * t4];
        const float b1 = g_bias[col0 + 2 * t4 + 1];
        #pragma unroll
        for (int mi = 0; mi < 2; mi++) {
            const int row = row0 + wr * 32 + mi * 16 + g;
            *(uint32_t*)&dst[(size_t)row * HH + h] =
                pack_h2((c[mi][ni][0] + b0) * sc, (c[mi][ni][1] + b1) * sc);
            *(uint32_t*)&dst[(size_t)(row + 8) * HH + h] =
                pack_h2((c[mi][ni][2] + b0) * sc, (c[mi][ni][3] + b1) * sc);
        }
    }
}

// ---------------------------------------------------------------------------
// Kernel 1b: transpose V -> g_vt[b][h][t]
// ---------------------------------------------------------------------------
__global__ void __launch_bounds__(256) vtrans_kernel()
{
    __shared__ __half ts[64][66];
    const int b  = blockIdx.y;
    const int s0 = blockIdx.x * 64;
    const int tid = threadIdx.x;

    const uint32_t* src = (const uint32_t*)(g_v + ((size_t)b * TT + s0) * HH);
    #pragma unroll
    for (int it = 0; it < 8; it++) {
        int i = tid + it * 256;
        int row = i >> 5, c = i & 31;
        *(uint32_t*)&ts[row][c * 2] = src[row * 32 + c];
    }
    __syncthreads();

    const int h = tid >> 2, sq = tid & 3;
    uint32_t* dst = (uint32_t*)(g_vt + ((size_t)b * HH + h) * TT + s0);
    #pragma unroll
    for (int j = 0; j < 8; j++) {
        int s = sq * 16 + 2 * j;
        uint32_t u = ((uint32_t)__half_as_ushort(ts[s + 1][h]) << 16)
                   | (uint32_t)__half_as_ushort(ts[s][h]);
        dst[sq * 8 + j] = u;
    }
}

// ---------------------------------------------------------------------------
// Kernel 2: fp16 mma flash attention v3.
//  8 warps x 16 t-rows; K-frags in regs; P stays in registers
//  (MMA1 C-frag -> half2 -> MMA2 A-frag); V pre-transposed; cp.async
//  double-buffered Q/Vt; 2 syncthreads per tile; 2 CTA/SM.
// ---------------------------------------------------------------------------
#define QSTRH 72                         // halfs per Q smem row
#define VSTRH 72
#define Q_HOFF(buf) ((buf) * 64 * QSTRH)
#define V_HOFF(buf) (2 * 64 * QSTRH + (buf) * 64 * VSTRH)
#define ATTN_SMEM_BYTES (4 * 64 * 72 * 2)   // 36864

__global__ void __launch_bounds__(256, 2) attn_kernel()
{
    extern __shared__ __half smh[];
    const uint32_t sbase = smem_u32(smh);

    const int tid  = threadIdx.x;
    const int warp = tid >> 5;
    const int lane = tid & 31;
    const int g  = lane >> 2;
    const int t4 = lane & 3;
    const int b  = blockIdx.y;
    const int t0 = blockIdx.x * 128;
    const int z  = blockIdx.z;

    const __half* qb  = g_q  + (size_t)b * TT * HH;
    const __half* vtb = g_vt + (size_t)b * HH * TT;

    auto issue_tile = [&](int tile, int buf) {
        const int s0 = (z * 32 + tile) * 64;
        #pragma unroll
        for (int it = 0; it < 2; it++) {
            int i = tid + it * 256;          // 0..511
            int row = i >> 3, c8 = i & 7;
            cp_async16(sbase + (Q_HOFF(buf) + row * QSTRH + c8 * 8) * 2,
                       qb + (size_t)(s0 + row) * HH + c8 * 8);
            cp_async16(sbase + (V_HOFF(buf) + row * VSTRH + c8 * 8) * 2,
                       vtb + (size_t)row * TT + s0 + c8 * 8);
        }
        CP_COMMIT();
    };

    issue_tile(0, 0);
    issue_tile(1, 1);

    // --- K fragments (fp16) to registers: warp owns rows [warp*16, +16) ---
    uint32_t kf[4][4];
    {
        const __half* kbp = g_k + ((size_t)(b * TT) + t0 + warp * 16) * HH;
        #pragma unroll
        for (int kb = 0; kb < 4; kb++) {
            const int k0 = kb * 16 + 2 * t4;
            kf[kb][0] = *(const uint32_t*)&kbp[(size_t)g * HH + k0];
            kf[kb][1] = *(const uint32_t*)&kbp[(size_t)(g + 8) * HH + k0];
            kf[kb][2] = *(const uint32_t*)&kbp[(size_t)g * HH + k0 + 8];
            kf[kb][3] = *(const uint32_t*)&kbp[(size_t)(g + 8) * HH + k0 + 8];
        }
    }

    float o[8][4];
    #pragma unroll
    for (int nj = 0; nj < 8; nj++)
        #pragma unroll
        for (int e = 0; e < 4; e++) o[nj][e] = 0.0f;
    float lsum0 = 0.f, lsum1 = 0.f;

    CP_WAIT1();
    __syncthreads();

    for (int tile = 0; tile < 32; tile++) {
        const int p = tile & 1;
        const uint32_t* qu = (const uint32_t*)(smh + Q_HOFF(p));
        const uint32_t* vu = (const uint32_t*)(smh + V_HOFF(p));

        // ---- MMA1: S[16t x 64s] = Kfrag . Q^T (4 k16-steps) ----
        float c[8][4];
        #pragma unroll
        for (int ni = 0; ni < 8; ni++)
            #pragma unroll
            for (int e = 0; e < 4; e++) c[ni][e] = 0.0f;

        #pragma unroll
        for (int kb = 0; kb < 4; kb++) {
            #pragma unroll
            for (int ni = 0; ni < 8; ni++) {
                const uint32_t* qp = qu + (ni * 8 + g) * (QSTRH / 2) + kb * 8 + t4;
                mma_f16(c[ni], kf[kb], qp[0], qp[4]);
            }
        }

        // ---- exp + pack: C-frag becomes MMA2 A-frag directly ----
        uint32_t pa[4][4];
        #pragma unroll
        for (int ni = 0; ni < 8; ni++) {
            const float e0 = ex2f(c[ni][0]);
            const float e1 = ex2f(c[ni][1]);
            const float e2 = ex2f(c[ni][2]);
            const float e3 = ex2f(c[ni][3]);
            lsum0 += e0 + e1;
            lsum1 += e2 + e3;
            pa[ni >> 1][(ni & 1) * 2 + 0] = pack_h2(e0, e1);
            pa[ni >> 1][(ni & 1) * 2 + 1] = pack_h2(e2, e3);
        }

        // ---- MMA2: O[16t x 64h] += P . V (Vt smem, k-major half2) ----
        #pragma unroll
        for (int kb = 0; kb < 4; kb++) {
            #pragma unroll
            for (int nj = 0; nj < 8; nj++) {
                const uint32_t* vp = vu + (nj * 8 + g) * (VSTRH / 2) + kb * 8 + t4;
                mma_f16(o[nj], pa[kb], vp[0], vp[4]);
            }
        }

        __syncthreads();               // all warps done reading buf p
        const int nt = (tile + 2 < 32) ? (tile + 2) : 31;
        issue_tile(nt, p);
        CP_WAIT1();
        __syncthreads();               // tile+1 buffer visible
    }

    // ---- epilogue: partial row sums + partial O ----
    lsum0 += __shfl_xor_sync(0xffffffffu, lsum0, 1);
    lsum0 += __shfl_xor_sync(0xffffffffu, lsum0, 2);
    lsum1 += __shfl_xor_sync(0xffffffffu, lsum1, 1);
    lsum1 += __shfl_xor_sync(0xffffffffu, lsum1, 2);

    const int row = t0 + warp * 16 + g;
    if (t4 == 0) {
        g_lpart[z * (BB * TT) + b * TT + row]     = lsum0;
        g_lpart[z * (BB * TT) + b * TT + row + 8] = lsum1;
    }
    float* ob = g_opart + (size_t)z * (BB * TT * HH) + (size_t)(b * TT + row) * HH;
    #pragma unroll
    for (int nj = 0; nj < 8; nj++) {
        const int col = nj * 8 + 2 * t4;
        *(float2*)&ob[col]          = make_float2(o[nj][0], o[nj][1]);
        *(float2*)&ob[8 * HH + col] = make_float2(o[nj][2], o[nj][3]);
    }
}

// ---------------------------------------------------------------------------
// Kernel 3: combine the two s-splits and normalize.
// ---------------------------------------------------------------------------
__global__ void __launch_bounds__(256) combine_kernel(float* __restrict__ out)
{
    const int i4 = blockIdx.x * 256 + threadIdx.x;
    const int row = i4 >> 4;
    const float inv = 1.0f / (g_lpart[row] + g_lpart[BB * TT + row]);
    const float4 a = ((const float4*)g_opart)[i4];
    const float4 c = ((const float4*)(g_opart + (size_t)BB * TT * HH))[i4];
    float4 r;
    r.x = (a.x + c.x) * inv;
    r.y = (a.y + c.y) * inv;
    r.z = (a.z + c.z) * inv;
    r.w = (a.w + c.w) * inv;
    ((float4*)out)[i4] = r;
}

// ---------------------------------------------------------------------------
extern "C" void kernel_launch(void* const* d_in, const int* in_sizes, int n_in,
                              void* d_out, int out_size)
{
    const float* x  = (const float*)d_in[0];
    const float* Wk = (const float*)d_in[1];
    const float* bk = (const float*)d_in[2];
    const float* Wq = (const float*)d_in[3];
    const float* bq = (const float*)d_in[4];
    const float* Wv = (const float*)d_in[5];
    const float* bv = (const float*)d_in[6];
    float* out = (float*)d_out;

    cudaFuncSetAttribute(qkv_mma_kernel, cudaFuncAttributeMaxDynamicSharedMemorySize,
                         QKV_SMEM_BYTES);
    cudaFuncSetAttribute(attn_kernel, cudaFuncAttributeMaxDynamicSharedMemorySize,
                         ATTN_SMEM_BYTES);

    wprep_kernel<<<192, 256>>>(Wk, bk, Wq, bq, Wv, bv);
    qkv_mma_kernel<<<(BB * TT) / 128, 512, QKV_SMEM_BYTES>>>(x);

    dim3 tgrid(TT / 64, BB);
    vtrans_kernel<<<tgrid, 256>>>();

    dim3 grid(TT / 128, BB, 2);
    attn_kernel<<<grid, 256, ATTN_SMEM_BYTES>>>();

    combine_kernel<<<(BB * TT * HH) / (4 * 256), 256>>>(out);
}

// round 8
// speedup vs baseline: 8.6940x; 1.0405x over previous
#include <cuda_runtime.h>
#include <cuda_fp16.h>
#include <cstdint>

// Problem constants: B=4, T=4096, C=256, H=64
#define BB 4
#define TT 4096
#define CC 256
#define HH 64
// k is pre-scaled by log2(e)/16 so softmax is a bare ex2 of the mma result.
#define KSCALE 0.09016844005556021f

// Scratch: fp16 projections (+ transposed V) + split-s partial outputs.
__device__ __half g_k[BB * TT * HH];
__device__ __half g_q[BB * TT * HH];
__device__ __half g_v[BB * TT * HH];
__device__ __half g_vt[BB * HH * TT];         // [b][h][t]
__device__ float  g_opart[2 * BB * TT * HH];  // 8MB
__device__ float  g_lpart[2 * BB * TT];
__device__ float  g_wt[192 * CC];             // W^T combined [h'][c], tf32
__device__ float  g_bias[192];

__device__ __forceinline__ uint32_t f2tf32(float f) {
    uint32_t r; asm("cvt.rna.tf32.f32 %0, %1;" : "=r"(r) : "f"(f)); return r;
}
__device__ __forceinline__ float ex2f(float x) {
    float r; asm("ex2.approx.f32 %0, %1;" : "=f"(r) : "f"(x)); return r;
}
__device__ __forceinline__ uint32_t pack_h2(float lo, float hi) {
    uint32_t r;
    asm("cvt.rn.f16x2.f32 %0, %1, %2;" : "=r"(r) : "f"(hi), "f"(lo));
    return r;
}
__device__ __forceinline__ uint32_t smem_u32(const void* p) {
    uint32_t a;
    asm("{ .reg .u64 t; cvta.to.shared.u64 t, %1; cvt.u32.u64 %0, t; }" : "=r"(a) : "l"(p));
    return a;
}
__device__ __forceinline__ void cp_async16(uint32_t dst, const void* src) {
    asm volatile("cp.async.cg.shared.global [%0], [%1], 16;"
                 :: "r"(dst), "l"(src) : "memory");
}
#define CP_COMMIT() asm volatile("cp.async.commit_group;" ::: "memory")
#define CP_WAIT1()  asm volatile("cp.async.wait_group 1;" ::: "memory")
#define CP_WAIT2()  asm volatile("cp.async.wait_group 2;" ::: "memory")

__device__ __forceinline__ void ldmx4(uint32_t* r, uint32_t addr) {
    asm volatile("ldmatrix.sync.aligned.m8n8.x4.shared.b16 {%0,%1,%2,%3}, [%4];"
                 : "=r"(r[0]), "=r"(r[1]), "=r"(r[2]), "=r"(r[3]) : "r"(addr));
}

// tf32 m16n8k8 (used by QKV GEMM)
__device__ __forceinline__ void mma_tf32(float* c, const uint32_t* a,
                                         uint32_t b0, uint32_t b1) {
    asm volatile(
        "mma.sync.aligned.m16n8k8.row.col.f32.tf32.tf32.f32 "
        "{%0,%1,%2,%3}, {%4,%5,%6,%7}, {%8,%9}, {%0,%1,%2,%3};"
        : "+f"(c[0]), "+f"(c[1]), "+f"(c[2]), "+f"(c[3])
        : "r"(a[0]), "r"(a[1]), "r"(a[2]), "r"(a[3]), "r"(b0), "r"(b1));
}
// fp16 m16n8k16 with fp32 accum (attention)
__device__ __forceinline__ void mma_f16(float* c, const uint32_t* a,
                                        uint32_t b0, uint32_t b1) {
    asm volatile(
        "mma.sync.aligned.m16n8k16.row.col.f32.f16.f16.f32 "
        "{%0,%1,%2,%3}, {%4,%5,%6,%7}, {%8,%9}, {%0,%1,%2,%3};"
        : "+f"(c[0]), "+f"(c[1]), "+f"(c[2]), "+f"(c[3])
        : "r"(a[0]), "r"(a[1]), "r"(a[2]), "r"(a[3]), "r"(b0), "r"(b1));
}

// ---------------------------------------------------------------------------
// Kernel 0: build W^T [192][256] (tf32-RNA) + combined bias.
// ---------------------------------------------------------------------------
__global__ void __launch_bounds__(256) wprep_kernel(
    const float* __restrict__ Wk, const float* __restrict__ bk,
    const float* __restrict__ Wq, const float* __restrict__ bq,
    const float* __restrict__ Wv, const float* __restrict__ bv)
{
    const int j = blockIdx.x;
    const int m = j >> 6;
    const int h = j & 63;
    const int c = threadIdx.x;
    const float* W = (m == 0) ? Wk : ((m == 1) ? Wq : Wv);
    g_wt[j * CC + c] = __uint_as_float(f2tf32(W[c * HH + h]));
    if (c == 0) {
        const float* bi = (m == 0) ? bk : ((m == 1) ? bq : bv);
        g_bias[j] = bi[h];
    }
}

// ---------------------------------------------------------------------------
// Kernel 1: QKV projection as tf32 GEMM [16384,256]x[256,192]; fp16 outputs.
// ---------------------------------------------------------------------------
#define XSTR 68
#define WSTR 68
#define QKV_SMEM_BYTES ((128 * XSTR + 192 * WSTR) * 4)   // 87040

__global__ void __launch_bounds__(512, 1) qkv_mma_kernel(const float* __restrict__ x)
{
    extern __shared__ float sm[];
    float* xs = sm;
    float* ws = sm + 128 * XSTR;

    const int tid  = threadIdx.x;
    const int warp = tid >> 5;
    const int lane = tid & 31;
    const int wr = warp & 3;
    const int wc = warp >> 2;
    const int g  = lane >> 2;
    const int t4 = lane & 3;
    const int row0 = blockIdx.x * 128;

    float c[2][6][4];
    #pragma unroll
    for (int mi = 0; mi < 2; mi++)
        #pragma unroll
        for (int ni = 0; ni < 6; ni++)
            #pragma unroll
            for (int e = 0; e < 4; e++) c[mi][ni][e] = 0.0f;

    const float4* x4  = (const float4*)x;
    const float4* wt4 = (const float4*)g_wt;
    const int arow = wr * 32 + g;

    #pragma unroll
    for (int kc = 0; kc < 4; kc++) {
        __syncthreads();
        #pragma unroll
        for (int it = 0; it < 4; it++) {
            int i = tid + it * 512;
            int row = i >> 4, c4 = i & 15;
            float4 v = x4[(size_t)(row0 + row) * (CC / 4) + kc * 16 + c4];
            v.x = __uint_as_float(f2tf32(v.x));
            v.y = __uint_as_float(f2tf32(v.y));
            v.z = __uint_as_float(f2tf32(v.z));
            v.w = __uint_as_float(f2tf32(v.w));
            *(float4*)&xs[row * XSTR + c4 * 4] = v;
        }
        #pragma unroll
        for (int it = 0; it < 6; it++) {
            int i = tid + it * 512;
            int j = i >> 4, c4 = i & 15;
            *(float4*)&ws[j * WSTR + c4 * 4] = wt4[j * (CC / 4) + kc * 16 + c4];
        }
        __syncthreads();

        #pragma unroll
        for (int k8 = 0; k8 < 8; k8++) {
            const int k0 = k8 * 8;
            uint32_t a[2][4];
            #pragma unroll
            for (int mi = 0; mi < 2; mi++) {
                const float* base = &xs[(arow + mi * 16) * XSTR + k0 + t4];
                a[mi][0] = __float_as_uint(base[0]);
                a[mi][1] = __float_as_uint(base[8 * XSTR]);
                a[mi][2] = __float_as_uint(base[4]);
                a[mi][3] = __float_as_uint(base[8 * XSTR + 4]);
            }
            #pragma unroll
            for (int ni = 0; ni < 6; ni++) {
                const float* wp = &ws[(wc * 48 + ni * 8 + g) * WSTR + k0 + t4];
                const uint32_t b0 = __float_as_uint(wp[0]);
                const uint32_t b1 = __float_as_uint(wp[4]);
                mma_tf32(c[0][ni], a[0], b0, b1);
                mma_tf32(c[1][ni], a[1], b0, b1);
            }
        }
    }

    #pragma unroll
    for (int ni = 0; ni < 6; ni++) {
        const int col0 = wc * 48 + ni * 8;
        const int m = col0 >> 6;
        __half* dst = (m == 0) ? g_k : ((m == 1) ? g_q : g_v);
        const float sc = (m == 0) ? KSCALE : 1.0f;
        const int h = (col0 & 63) + 2 * t4;
        const float b0 = g_bias[col0 + 2 * t4];
        const float b1 = g_bias[col0 + 2 * t4 + 1];
        #pragma unroll
        for (int mi = 0; mi < 2; mi++) {
            const int row = row0 + wr * 32 + mi * 16 + g;
            *(uint32_t*)&dst[(size_t)row * HH + h] =
                pack_h2((c[mi][ni][0] + b0) * sc, (c[mi][ni][1] + b1) * sc);
            *(uint32_t*)&dst[(size_t)(row + 8) * HH + h] =
                pack_h2((c[mi][ni][2] + b0) * sc, (c[mi][ni][3] + b1) * sc);
        }
    }
}

// ---------------------------------------------------------------------------
// Kernel 1b: transpose V -> g_vt[b][h][t]
// ---------------------------------------------------------------------------
__global__ void __launch_bounds__(256) vtrans_kernel()
{
    __shared__ __half ts[64][66];
    const int b  = blockIdx.y;
    const int s0 = blockIdx.x * 64;
    const int tid = threadIdx.x;

    const uint32_t* src = (const uint32_t*)(g_v + ((size_t)b * TT + s0) * HH);
    #pragma unroll
    for (int it = 0; it < 8; it++) {
        int i = tid + it * 256;
        int row = i >> 5, c = i & 31;
        *(uint32_t*)&ts[row][c * 2] = src[row * 32 + c];
    }
    __syncthreads();

    const int h = tid >> 2, sq = tid & 3;
    uint32_t* dst = (uint32_t*)(g_vt + ((size_t)b * HH + h) * TT + s0);
    #pragma unroll
    for (int j = 0; j < 8; j++) {
        int s = sq * 16 + 2 * j;
        uint32_t u = ((uint32_t)__half_as_ushort(ts[s + 1][h]) << 16)
                   | (uint32_t)__half_as_ushort(ts[s][h]);
        dst[sq * 8 + j] = u;
    }
}

// ---------------------------------------------------------------------------
// Kernel 2: fp16 mma flash attention v4.
//  ldmatrix.x4 fragment loads; row-sums via ones-column MMA; 4-stage
//  cp.async pipeline with ONE syncthreads per tile; P in registers.
//  8 warps x 16 t-rows; 2 CTA/SM.
// ---------------------------------------------------------------------------
#define QSTRH 72                      // halves per smem row (Q and Vt)
#define STAGE_H (64 * QSTRH * 2)      // one stage: Q tile + V tile (halves)
#define Q_HOFF(buf) ((buf) * STAGE_H)
#define V_HOFF(buf) ((buf) * STAGE_H + 64 * QSTRH)
#define ATTN_SMEM_BYTES (4 * STAGE_H * 2)   // 73728

__global__ void __launch_bounds__(256, 2) attn_kernel()
{
    extern __shared__ __half smh[];
    const uint32_t sbase = smem_u32(smh);

    const int tid  = threadIdx.x;
    const int warp = tid >> 5;
    const int lane = tid & 31;
    const int g  = lane >> 2;
    const int t4 = lane & 3;
    const int b  = blockIdx.y;
    const int t0 = blockIdx.x * 128;
    const int z  = blockIdx.z;

    const __half* qb  = g_q  + (size_t)b * TT * HH;
    const __half* vtb = g_vt + (size_t)b * HH * TT;

    auto issue_tile = [&](int tile, int buf) {
        const int s0 = (z * 32 + tile) * 64;
        #pragma unroll
        for (int it = 0; it < 2; it++) {
            int i = tid + it * 256;          // 0..511
            int row = i >> 3, c8 = i & 7;
            cp_async16(sbase + (Q_HOFF(buf) + row * QSTRH + c8 * 8) * 2,
                       qb + (size_t)(s0 + row) * HH + c8 * 8);
            cp_async16(sbase + (V_HOFF(buf) + row * QSTRH + c8 * 8) * 2,
                       vtb + (size_t)row * TT + s0 + c8 * 8);
        }
        CP_COMMIT();
    };

    issue_tile(0, 0);
    issue_tile(1, 1);
    issue_tile(2, 2);

    // --- K fragments (fp16) to registers: warp owns rows [warp*16, +16) ---
    uint32_t kf[4][4];
    {
        const __half* kbp = g_k + ((size_t)(b * TT) + t0 + warp * 16) * HH;
        #pragma unroll
        for (int kb = 0; kb < 4; kb++) {
            const int k0 = kb * 16 + 2 * t4;
            kf[kb][0] = *(const uint32_t*)&kbp[(size_t)g * HH + k0];
            kf[kb][1] = *(const uint32_t*)&kbp[(size_t)(g + 8) * HH + k0];
            kf[kb][2] = *(const uint32_t*)&kbp[(size_t)g * HH + k0 + 8];
            kf[kb][3] = *(const uint32_t*)&kbp[(size_t)(g + 8) * HH + k0 + 8];
        }
    }

    float o[8][4];
    #pragma unroll
    for (int nj = 0; nj < 8; nj++)
        #pragma unroll
        for (int e = 0; e < 4; e++) o[nj][e] = 0.0f;
    float ol[4] = {0.f, 0.f, 0.f, 0.f};           // ones-column: row sums
    const uint32_t ones = (g == 0) ? 0x3C003C00u : 0u;

    // ldmatrix per-lane byte offset: rows (lane&7) [+8 if lane>=16],
    // +16B column offset if (lane>>3)&1.
    const uint32_t lmlane =
        ((((lane >> 4) & 1) * 8 + (lane & 7)) * QSTRH) * 2 + ((lane >> 3) & 1) * 16;

    for (int tile = 0; tile < 32; tile++) {
        const int buf = tile & 3;
        CP_WAIT2();
        __syncthreads();
        if (tile + 3 < 32) issue_tile(tile + 3, (tile + 3) & 3);
        else CP_COMMIT();

        const uint32_t qbase = sbase + Q_HOFF(buf) * 2 + lmlane;
        const uint32_t vbase = sbase + V_HOFF(buf) * 2 + lmlane;

        // ---- MMA1 + softmax in two ni-halves; P packs into MMA2 A-frags ----
        uint32_t pa[4][4];
        #pragma unroll
        for (int nh = 0; nh < 2; nh++) {
            float c[4][4];
            #pragma unroll
            for (int j = 0; j < 4; j++)
                #pragma unroll
                for (int e = 0; e < 4; e++) c[j][e] = 0.0f;

            #pragma unroll
            for (int kb = 0; kb < 4; kb++) {
                uint32_t q0[4], q1[4];
                ldmx4(q0, qbase + (2 * nh)     * (16 * QSTRH * 2) + kb * 32);
                ldmx4(q1, qbase + (2 * nh + 1) * (16 * QSTRH * 2) + kb * 32);
                mma_f16(c[0], kf[kb], q0[0], q0[1]);
                mma_f16(c[1], kf[kb], q0[2], q0[3]);
                mma_f16(c[2], kf[kb], q1[0], q1[1]);
                mma_f16(c[3], kf[kb], q1[2], q1[3]);
            }
            #pragma unroll
            for (int j = 0; j < 4; j++) {
                const int ni = nh * 4 + j;
                const float e0 = ex2f(c[j][0]);
                const float e1 = ex2f(c[j][1]);
                const float e2 = ex2f(c[j][2]);
                const float e3 = ex2f(c[j][3]);
                pa[ni >> 1][(ni & 1) * 2 + 0] = pack_h2(e0, e1);
                pa[ni >> 1][(ni & 1) * 2 + 1] = pack_h2(e2, e3);
            }
        }

        // ---- MMA2: O[16t x 64h] += P . V^T ; +ones column for row sums ----
        #pragma unroll
        for (int kb = 0; kb < 4; kb++) {
            #pragma unroll
            for (int m = 0; m < 4; m++) {
                uint32_t vf[4];
                ldmx4(vf, vbase + m * (16 * QSTRH * 2) + kb * 32);
                mma_f16(o[2 * m],     pa[kb], vf[0], vf[1]);
                mma_f16(o[2 * m + 1], pa[kb], vf[2], vf[3]);
            }
            mma_f16(ol, pa[kb], ones, ones);
        }
    }

    // ---- epilogue: row sums from ones-column; partial O to scratch ----
    const int row = t0 + warp * 16 + g;
    if (t4 == 0) {
        g_lpart[z * (BB * TT) + b * TT + row]     = ol[0];
        g_lpart[z * (BB * TT) + b * TT + row + 8] = ol[2];
    }
    float* ob = g_opart + (size_t)z * (BB * TT * HH) + (size_t)(b * TT + row) * HH;
    #pragma unroll
    for (int nj = 0; nj < 8; nj++) {
        const int col = nj * 8 + 2 * t4;
        *(float2*)&ob[col]          = make_float2(o[nj][0], o[nj][1]);
        *(float2*)&ob[8 * HH + col] = make_float2(o[nj][2], o[nj][3]);
    }
}

// ---------------------------------------------------------------------------
// Kernel 3: combine the two s-splits and normalize.
// ---------------------------------------------------------------------------
__global__ void __launch_bounds__(256) combine_kernel(float* __restrict__ out)
{
    const int i4 = blockIdx.x * 256 + threadIdx.x;
    const int row = i4 >> 4;
    const float inv = 1.0f / (g_lpart[row] + g_lpart[BB * TT + row]);
    const float4 a = ((const float4*)g_opart)[i4];
    const float4 c = ((const float4*)(g_opart + (size_t)BB * TT * HH))[i4];
    float4 r;
    r.x = (a.x + c.x) * inv;
    r.y = (a.y + c.y) * inv;
    r.z = (a.z + c.z) * inv;
    r.w = (a.w + c.w) * inv;
    ((float4*)out)[i4] = r;
}

// ---------------------------------------------------------------------------
extern "C" void kernel_launch(void* const* d_in, const int* in_sizes, int n_in,
                              void* d_out, int out_size)
{
    const float* x  = (const float*)d_in[0];
    const float* Wk = (const float*)d_in[1];
    const float* bk = (const float*)d_in[2];
    const float* Wq = (const float*)d_in[3];
    const float* bq = (const float*)d_in[4];
    const float* Wv = (const float*)d_in[5];
    const float* bv = (const float*)d_in[6];
    float* out = (float*)d_out;

    cudaFuncSetAttribute(qkv_mma_kernel, cudaFuncAttributeMaxDynamicSharedMemorySize,
                         QKV_SMEM_BYTES);
    cudaFuncSetAttribute(attn_kernel, cudaFuncAttributeMaxDynamicSharedMemorySize,
                         ATTN_SMEM_BYTES);

    wprep_kernel<<<192, 256>>>(Wk, bk, Wq, bq, Wv, bv);
    qkv_mma_kernel<<<(BB * TT) / 128, 512, QKV_SMEM_BYTES>>>(x);

    dim3 tgrid(TT / 64, BB);
    vtrans_kernel<<<tgrid, 256>>>();

    dim3 grid(TT / 128, BB, 2);
    attn_kernel<<<grid, 256, ATTN_SMEM_BYTES>>>();

    combine_kernel<<<(BB * TT * HH) / (4 * 256), 256>>>(out);
}

// round 9
// speedup vs baseline: 8.7541x; 1.0069x over previous
#include <cuda_runtime.h>
#include <cuda_fp16.h>
#include <cstdint>

// Problem constants: B=4, T=4096, C=256, H=64
#define BB 4
#define TT 4096
#define CC 256
#define HH 64
// k is pre-scaled by log2(e)/16 so softmax is a bare ex2 of the mma result.
#define KSCALE 0.09016844005556021f

// Scratch: fp16 projections (+ transposed V) + split-s partial outputs.
__device__ __half g_k[BB * TT * HH];
__device__ __half g_q[BB * TT * HH];
__device__ __half g_v[BB * TT * HH];
__device__ __half g_vt[BB * HH * TT];         // [b][h][t]
__device__ float  g_opart[2 * BB * TT * HH];  // 8MB
__device__ float  g_lpart[2 * BB * TT];
__device__ float  g_wt[192 * CC];             // W^T combined [h'][c], tf32
__device__ float  g_bias[192];

__device__ __forceinline__ uint32_t f2tf32(float f) {
    uint32_t r; asm("cvt.rna.tf32.f32 %0, %1;" : "=r"(r) : "f"(f)); return r;
}
__device__ __forceinline__ uint32_t pack_h2(float lo, float hi) {
    uint32_t r;
    asm("cvt.rn.f16x2.f32 %0, %1, %2;" : "=r"(r) : "f"(hi), "f"(lo));
    return r;
}
__device__ __forceinline__ uint32_t h2exp2(uint32_t x) {
    uint32_t r;
    asm("ex2.approx.f16x2 %0, %1;" : "=r"(r) : "r"(x));
    return r;
}
__device__ __forceinline__ uint32_t smem_u32(const void* p) {
    uint32_t a;
    asm("{ .reg .u64 t; cvta.to.shared.u64 t, %1; cvt.u32.u64 %0, t; }" : "=r"(a) : "l"(p));
    return a;
}
__device__ __forceinline__ void cp_async16(uint32_t dst, const void* src) {
    asm volatile("cp.async.cg.shared.global [%0], [%1], 16;"
                 :: "r"(dst), "l"(src) : "memory");
}
#define CP_COMMIT() asm volatile("cp.async.commit_group;" ::: "memory")
#define CP_WAIT2()  asm volatile("cp.async.wait_group 2;" ::: "memory")

__device__ __forceinline__ void ldmx4(uint32_t* r, uint32_t addr) {
    asm volatile("ldmatrix.sync.aligned.m8n8.x4.shared.b16 {%0,%1,%2,%3}, [%4];"
                 : "=r"(r[0]), "=r"(r[1]), "=r"(r[2]), "=r"(r[3]) : "r"(addr)
                 : "memory");
}

// tf32 m16n8k8 (used by QKV GEMM)
__device__ __forceinline__ void mma_tf32(float* c, const uint32_t* a,
                                         uint32_t b0, uint32_t b1) {
    asm volatile(
        "mma.sync.aligned.m16n8k8.row.col.f32.tf32.tf32.f32 "
        "{%0,%1,%2,%3}, {%4,%5,%6,%7}, {%8,%9}, {%0,%1,%2,%3};"
        : "+f"(c[0]), "+f"(c[1]), "+f"(c[2]), "+f"(c[3])
        : "r"(a[0]), "r"(a[1]), "r"(a[2]), "r"(a[3]), "r"(b0), "r"(b1));
}
// fp16 m16n8k16 with fp32 accum (attention). Non-volatile: pure register op,
// all dependencies expressed -> compiler may schedule across softmax code.
__device__ __forceinline__ void mma_f16(float* c, const uint32_t* a,
                                        uint32_t b0, uint32_t b1) {
    asm("mma.sync.aligned.m16n8k16.row.col.f32.f16.f16.f32 "
        "{%0,%1,%2,%3}, {%4,%5,%6,%7}, {%8,%9}, {%0,%1,%2,%3};"
        : "+f"(c[0]), "+f"(c[1]), "+f"(c[2]), "+f"(c[3])
        : "r"(a[0]), "r"(a[1]), "r"(a[2]), "r"(a[3]), "r"(b0), "r"(b1));
}

// ---------------------------------------------------------------------------
// Kernel 0: build W^T [192][256] (tf32-RNA) + combined bias.
// ---------------------------------------------------------------------------
__global__ void __launch_bounds__(256) wprep_kernel(
    const float* __restrict__ Wk, const float* __restrict__ bk,
    const float* __restrict__ Wq, const float* __restrict__ bq,
    const float* __restrict__ Wv, const float* __restrict__ bv)
{
    const int j = blockIdx.x;
    const int m = j >> 6;
    const int h = j & 63;
    const int c = threadIdx.x;
    const float* W = (m == 0) ? Wk : ((m == 1) ? Wq : Wv);
    g_wt[j * CC + c] = __uint_as_float(f2tf32(W[c * HH + h]));
    if (c == 0) {
        const float* bi = (m == 0) ? bk : ((m == 1) ? bq : bv);
        g_bias[j] = bi[h];
    }
}

// ---------------------------------------------------------------------------
// Kernel 1: QKV projection as tf32 GEMM [16384,256]x[256,192]; fp16 outputs.
// ---------------------------------------------------------------------------
#define XSTR 68
#define WSTR 68
#define QKV_SMEM_BYTES ((128 * XSTR + 192 * WSTR) * 4)   // 87040

__global__ void __launch_bounds__(512, 1) qkv_mma_kernel(const float* __restrict__ x)
{
    extern __shared__ float sm[];
    float* xs = sm;
    float* ws = sm + 128 * XSTR;

    const int tid  = threadIdx.x;
    const int warp = tid >> 5;
    const int lane = tid & 31;
    const int wr = warp & 3;
    const int wc = warp >> 2;
    const int g  = lane >> 2;
    const int t4 = lane & 3;
    const int row0 = blockIdx.x * 128;

    float c[2][6][4];
    #pragma unroll
    for (int mi = 0; mi < 2; mi++)
        #pragma unroll
        for (int ni = 0; ni < 6; ni++)
            #pragma unroll
            for (int e = 0; e < 4; e++) c[mi][ni][e] = 0.0f;

    const float4* x4  = (const float4*)x;
    const float4* wt4 = (const float4*)g_wt;
    const int arow = wr * 32 + g;

    #pragma unroll
    for (int kc = 0; kc < 4; kc++) {
        __syncthreads();
        #pragma unroll
        for (int it = 0; it < 4; it++) {
            int i = tid + it * 512;
            int row = i >> 4, c4 = i & 15;
            float4 v = x4[(size_t)(row0 + row) * (CC / 4) + kc * 16 + c4];
            v.x = __uint_as_float(f2tf32(v.x));
            v.y = __uint_as_float(f2tf32(v.y));
            v.z = __uint_as_float(f2tf32(v.z));
            v.w = __uint_as_float(f2tf32(v.w));
            *(float4*)&xs[row * XSTR + c4 * 4] = v;
        }
        #pragma unroll
        for (int it = 0; it < 6; it++) {
            int i = tid + it * 512;
            int j = i >> 4, c4 = i & 15;
            *(float4*)&ws[j * WSTR + c4 * 4] = wt4[j * (CC / 4) + kc * 16 + c4];
        }
        __syncthreads();

        #pragma unroll
        for (int k8 = 0; k8 < 8; k8++) {
            const int k0 = k8 * 8;
            uint32_t a[2][4];
            #pragma unroll
            for (int mi = 0; mi < 2; mi++) {
                const float* base = &xs[(arow + mi * 16) * XSTR + k0 + t4];
                a[mi][0] = __float_as_uint(base[0]);
                a[mi][1] = __float_as_uint(base[8 * XSTR]);
                a[mi][2] = __float_as_uint(base[4]);
                a[mi][3] = __float_as_uint(base[8 * XSTR + 4]);
            }
            #pragma unroll
            for (int ni = 0; ni < 6; ni++) {
                const float* wp = &ws[(wc * 48 + ni * 8 + g) * WSTR + k0 + t4];
                const uint32_t b0 = __float_as_uint(wp[0]);
                const uint32_t b1 = __float_as_uint(wp[4]);
                mma_tf32(c[0][ni], a[0], b0, b1);
                mma_tf32(c[1][ni], a[1], b0, b1);
            }
        }
    }

    #pragma unroll
    for (int ni = 0; ni < 6; ni++) {
        const int col0 = wc * 48 + ni * 8;
        const int m = col0 >> 6;
        __half* dst = (m == 0) ? g_k : ((m == 1) ? g_q : g_v);
        const float sc = (m == 0) ? KSCALE : 1.0f;
        const int h = (col0 & 63) + 2 * t4;
        const float b0 = g_bias[col0 + 2 * t4];
        const float b1 = g_bias[col0 + 2 * t4 + 1];
        #pragma unroll
        for (int mi = 0; mi < 2; mi++) {
            const int row = row0 + wr * 32 + mi * 16 + g;
            *(uint32_t*)&dst[(size_t)row * HH + h] =
                pack_h2((c[mi][ni][0] + b0) * sc, (c[mi][ni][1] + b1) * sc);
            *(uint32_t*)&dst[(size_t)(row + 8) * HH + h] =
                pack_h2((c[mi][ni][2] + b0) * sc, (c[mi][ni][3] + b1) * sc);
        }
    }
}

// ---------------------------------------------------------------------------
// Kernel 1b: transpose V -> g_vt[b][h][t]
// ---------------------------------------------------------------------------
__global__ void __launch_bounds__(256) vtrans_kernel()
{
    __shared__ __half ts[64][66];
    const int b  = blockIdx.y;
    const int s0 = blockIdx.x * 64;
    const int tid = threadIdx.x;

    const uint32_t* src = (const uint32_t*)(g_v + ((size_t)b * TT + s0) * HH);
    #pragma unroll
    for (int it = 0; it < 8; it++) {
        int i = tid + it * 256;
        int row = i >> 5, c = i & 31;
        *(uint32_t*)&ts[row][c * 2] = src[row * 32 + c];
    }
    __syncthreads();

    const int h = tid >> 2, sq = tid & 3;
    uint32_t* dst = (uint32_t*)(g_vt + ((size_t)b * HH + h) * TT + s0);
    #pragma unroll
    for (int j = 0; j < 8; j++) {
        int s = sq * 16 + 2 * j;
        uint32_t u = ((uint32_t)__half_as_ushort(ts[s + 1][h]) << 16)
                   | (uint32_t)__half_as_ushort(ts[s][h]);
        dst[sq * 8 + j] = u;
    }
}

// ---------------------------------------------------------------------------
// Kernel 2: fp16 mma flash attention v5.
//  ldmatrix.x4; f16x2 exp (pack-then-exp); ones-column row sums; 4-stage
//  cp.async pipeline, one syncthreads per tile; P in registers; 2 CTA/SM.
// ---------------------------------------------------------------------------
#define QSTRH 72                      // halves per smem row (Q and Vt)
#define STAGE_H (64 * QSTRH * 2)      // one stage: Q tile + V tile (halves)
#define Q_HOFF(buf) ((buf) * STAGE_H)
#define V_HOFF(buf) ((buf) * STAGE_H + 64 * QSTRH)
#define ATTN_SMEM_BYTES (4 * STAGE_H * 2)   // 73728

__global__ void __launch_bounds__(256, 2) attn_kernel()
{
    extern __shared__ __half smh[];
    const uint32_t sbase = smem_u32(smh);

    const int tid  = threadIdx.x;
    const int warp = tid >> 5;
    const int lane = tid & 31;
    const int g  = lane >> 2;
    const int t4 = lane & 3;
    const int b  = blockIdx.y;
    const int t0 = blockIdx.x * 128;
    const int z  = blockIdx.z;

    const __half* qb  = g_q  + (size_t)b * TT * HH;
    const __half* vtb = g_vt + (size_t)b * HH * TT;

    auto issue_tile = [&](int tile, int buf) {
        const int s0 = (z * 32 + tile) * 64;
        #pragma unroll
        for (int it = 0; it < 2; it++) {
            int i = tid + it * 256;          // 0..511
            int row = i >> 3, c8 = i & 7;
            cp_async16(sbase + (Q_HOFF(buf) + row * QSTRH + c8 * 8) * 2,
                       qb + (size_t)(s0 + row) * HH + c8 * 8);
            cp_async16(sbase + (V_HOFF(buf) + row * QSTRH + c8 * 8) * 2,
                       vtb + (size_t)row * TT + s0 + c8 * 8);
        }
        CP_COMMIT();
    };

    issue_tile(0, 0);
    issue_tile(1, 1);
    issue_tile(2, 2);

    // --- K fragments (fp16) to registers: warp owns rows [warp*16, +16) ---
    uint32_t kf[4][4];
    {
        const __half* kbp = g_k + ((size_t)(b * TT) + t0 + warp * 16) * HH;
        #pragma unroll
        for (int kb = 0; kb < 4; kb++) {
            const int k0 = kb * 16 + 2 * t4;
            kf[kb][0] = *(const uint32_t*)&kbp[(size_t)g * HH + k0];
            kf[kb][1] = *(const uint32_t*)&kbp[(size_t)(g + 8) * HH + k0];
            kf[kb][2] = *(const uint32_t*)&kbp[(size_t)g * HH + k0 + 8];
            kf[kb][3] = *(const uint32_t*)&kbp[(size_t)(g + 8) * HH + k0 + 8];
        }
    }

    float o[8][4];
    #pragma unroll
    for (int nj = 0; nj < 8; nj++)
        #pragma unroll
        for (int e = 0; e < 4; e++) o[nj][e] = 0.0f;
    float ol[4] = {0.f, 0.f, 0.f, 0.f};           // ones-column: row sums
    const uint32_t ones = (g == 0) ? 0x3C003C00u : 0u;

    // ldmatrix per-lane byte offset: rows (lane&7) [+8 if lane>=16],
    // +16B column offset if (lane>>3)&1.
    const uint32_t lmlane =
        ((((lane >> 4) & 1) * 8 + (lane & 7)) * QSTRH) * 2 + ((lane >> 3) & 1) * 16;

    for (int tile = 0; tile < 32; tile++) {
        const int buf = tile & 3;
        CP_WAIT2();
        __syncthreads();
        if (tile + 3 < 32) issue_tile(tile + 3, (tile + 3) & 3);
        else CP_COMMIT();

        const uint32_t qbase = sbase + Q_HOFF(buf) * 2 + lmlane;
        const uint32_t vbase = sbase + V_HOFF(buf) * 2 + lmlane;

        // ---- MMA1 + softmax in two ni-halves; P packs into MMA2 A-frags ----
        uint32_t pa[4][4];
        #pragma unroll
        for (int nh = 0; nh < 2; nh++) {
            float c[4][4];
            #pragma unroll
            for (int j = 0; j < 4; j++)
                #pragma unroll
                for (int e = 0; e < 4; e++) c[j][e] = 0.0f;

            #pragma unroll
            for (int kb = 0; kb < 4; kb++) {
                uint32_t q0[4], q1[4];
                ldmx4(q0, qbase + (2 * nh)     * (16 * QSTRH * 2) + kb * 32);
                ldmx4(q1, qbase + (2 * nh + 1) * (16 * QSTRH * 2) + kb * 32);
                mma_f16(c[0], kf[kb], q0[0], q0[1]);
                mma_f16(c[1], kf[kb], q0[2], q0[3]);
                mma_f16(c[2], kf[kb], q1[0], q1[1]);
                mma_f16(c[3], kf[kb], q1[2], q1[3]);
            }
            // pack logits to f16x2, then one MUFU per pair
            #pragma unroll
            for (int j = 0; j < 4; j++) {
                const int ni = nh * 4 + j;
                pa[ni >> 1][(ni & 1) * 2 + 0] = h2exp2(pack_h2(c[j][0], c[j][1]));
                pa[ni >> 1][(ni & 1) * 2 + 1] = h2exp2(pack_h2(c[j][2], c[j][3]));
            }
        }

        // ---- MMA2: O[16t x 64h] += P . V^T ; +ones column for row sums ----
        #pragma unroll
        for (int kb = 0; kb < 4; kb++) {
            #pragma unroll
            for (int m = 0; m < 4; m++) {
                uint32_t vf[4];
                ldmx4(vf, vbase + m * (16 * QSTRH * 2) + kb * 32);
                mma_f16(o[2 * m],     pa[kb], vf[0], vf[1]);
                mma_f16(o[2 * m + 1], pa[kb], vf[2], vf[3]);
            }
            mma_f16(ol, pa[kb], ones, ones);
        }
    }

    // ---- epilogue: row sums from ones-column; partial O to scratch ----
    const int row = t0 + warp * 16 + g;
    if (t4 == 0) {
        g_lpart[z * (BB * TT) + b * TT + row]     = ol[0];
        g_lpart[z * (BB * TT) + b * TT + row + 8] = ol[2];
    }
    float* ob = g_opart + (size_t)z * (BB * TT * HH) + (size_t)(b * TT + row) * HH;
    #pragma unroll
    for (int nj = 0; nj < 8; nj++) {
        const int col = nj * 8 + 2 * t4;
        *(float2*)&ob[col]          = make_float2(o[nj][0], o[nj][1]);
        *(float2*)&ob[8 * HH + col] = make_float2(o[nj][2], o[nj][3]);
    }
}

// ---------------------------------------------------------------------------
// Kernel 3: combine the two s-splits and normalize.
// ---------------------------------------------------------------------------
__global__ void __launch_bounds__(256) combine_kernel(float* __restrict__ out)
{
    const int i4 = blockIdx.x * 256 + threadIdx.x;
    const int row = i4 >> 4;
    const float inv = 1.0f / (g_lpart[row] + g_lpart[BB * TT + row]);
    const float4 a = ((const float4*)g_opart)[i4];
    const float4 c = ((const float4*)(g_opart + (size_t)BB * TT * HH))[i4];
    float4 r;
    r.x = (a.x + c.x) * inv;
    r.y = (a.y + c.y) * inv;
    r.z = (a.z + c.z) * inv;
    r.w = (a.w + c.w) * inv;
    ((float4*)out)[i4] = r;
}

// ---------------------------------------------------------------------------
extern "C" void kernel_launch(void* const* d_in, const int* in_sizes, int n_in,
                              void* d_out, int out_size)
{
    const float* x  = (const float*)d_in[0];
    const float* Wk = (const float*)d_in[1];
    const float* bk = (const float*)d_in[2];
    const float* Wq = (const float*)d_in[3];
    const float* bq = (const float*)d_in[4];
    const float* Wv = (const float*)d_in[5];
    const float* bv = (const float*)d_in[6];
    float* out = (float*)d_out;

    cudaFuncSetAttribute(qkv_mma_kernel, cudaFuncAttributeMaxDynamicSharedMemorySize,
                         QKV_SMEM_BYTES);
    cudaFuncSetAttribute(attn_kernel, cudaFuncAttributeMaxDynamicSharedMemorySize,
                         ATTN_SMEM_BYTES);

    wprep_kernel<<<192, 256>>>(Wk, bk, Wq, bq, Wv, bv);
    qkv_mma_kernel<<<(BB * TT) / 128, 512, QKV_SMEM_BYTES>>>(x);

    dim3 tgrid(TT / 64, BB);
    vtrans_kernel<<<tgrid, 256>>>();

    dim3 grid(TT / 128, BB, 2);
    attn_kernel<<<grid, 256, ATTN_SMEM_BYTES>>>();

    combine_kernel<<<(BB * TT * HH) / (4 * 256), 256>>>(out);
}